// round 2
// baseline (speedup 1.0000x reference)
#include <cuda_runtime.h>
#include <math.h>

#define BB 8
#define CC 512
#define DD 64
#define HWN 2304  // 48*48

// ---------------- scratch (static device globals; no allocation) ----------------
__device__ float g_q  [(size_t)BB*HWN*DD];
__device__ float g_kt [(size_t)BB*HWN*DD];
__device__ float g_attn[(size_t)BB*HWN*HWN];     // reused for scores
__device__ float g_v1 [(size_t)BB*CC*HWN];
__device__ float g_v2 [(size_t)BB*CC*HWN];
__device__ float g_x1 [(size_t)BB*CC*HWN];
__device__ float g_x2 [(size_t)BB*CC*HWN];
__device__ float g_q2 [(size_t)BB*HWN*CC];
__device__ float g_k2 [(size_t)BB*HWN*CC];
__device__ float g_v2f[(size_t)BB*HWN*CC];
__device__ float g_mid[(size_t)BB*HWN*CC];
__device__ float g_mid2[(size_t)BB*HWN*CC];
__device__ float g_pp [(size_t)BB*18*CC];
__device__ float g_pm [BB*18];
__device__ float g_proto[BB*CC];
__device__ float g_qp [BB*CC];
__device__ float g_kp [BB*CC];
__device__ float g_vp [BB*CC];
__device__ float g_aw [BB];

// ---------------- generic strided SGEMM: C[i,j] = alpha*sum_k A[i,k]*B[k,j] (+bias)(+res) ----
#define TM 128
#define TN 128
#define TKK 16

__global__ __launch_bounds__(256)
void sgemm_kernel(int M, int N, int K,
                  const float* __restrict__ A, long sa_r, long sa_c, long bsA,
                  const float* __restrict__ Bm, long sb_r, long sb_c, long bsB,
                  float* __restrict__ Cm, long ldc, long bsC,
                  const float* __restrict__ bias, int bias_mode,   // 0 none, 1 per-col(j), 2 per-row(i)
                  const float* __restrict__ alpha_ptr, float alpha_const,
                  const float* __restrict__ Rm, long ldr, long bsR)
{
    __shared__ float As[TKK][TM + 1];
    __shared__ float Bs[TKK][TN + 1];
    int bz = blockIdx.z;
    A  += (long)bz * bsA;
    Bm += (long)bz * bsB;
    Cm += (long)bz * bsC;
    if (Rm) Rm += (long)bz * bsR;

    int i0 = blockIdx.y * TM, j0 = blockIdx.x * TN;
    int tid = threadIdx.x;
    int tr = (tid / 16) * 8, tc = (tid % 16) * 8;

    float acc[8][8];
#pragma unroll
    for (int x = 0; x < 8; x++)
#pragma unroll
        for (int y = 0; y < 8; y++) acc[x][y] = 0.f;

    for (int k0 = 0; k0 < K; k0 += TKK) {
        // ---- load A tile (pick coalesced direction) ----
        if (sa_c == 1) {
#pragma unroll
            for (int t = tid; t < TM * TKK; t += 256) {
                int kk = t & (TKK - 1), i = t >> 4;
                int gi = i0 + i, gk = k0 + kk;
                As[kk][i] = (gi < M) ? A[(long)gi * sa_r + gk] : 0.f;
            }
        } else {  // sa_r == 1
#pragma unroll
            for (int t = tid; t < TM * TKK; t += 256) {
                int i = t & (TM - 1), kk = t >> 7;
                int gi = i0 + i, gk = k0 + kk;
                As[kk][i] = (gi < M) ? A[(long)gi + (long)gk * sa_c] : 0.f;
            }
        }
        // ---- load B tile ----
        if (sb_c == 1) {
#pragma unroll
            for (int t = tid; t < TN * TKK; t += 256) {
                int j = t & (TN - 1), kk = t >> 7;
                int gj = j0 + j, gk = k0 + kk;
                Bs[kk][j] = (gj < N) ? Bm[(long)gk * sb_r + gj] : 0.f;
            }
        } else {  // sb_r == 1
#pragma unroll
            for (int t = tid; t < TN * TKK; t += 256) {
                int kk = t & (TKK - 1), j = t >> 4;
                int gj = j0 + j, gk = k0 + kk;
                Bs[kk][j] = (gj < N) ? Bm[(long)gk + (long)gj * sb_c] : 0.f;
            }
        }
        __syncthreads();
#pragma unroll
        for (int kk = 0; kk < TKK; kk++) {
            float a[8], b[8];
#pragma unroll
            for (int x = 0; x < 8; x++) a[x] = As[kk][tr + x];
#pragma unroll
            for (int y = 0; y < 8; y++) b[y] = Bs[kk][tc + y];
#pragma unroll
            for (int x = 0; x < 8; x++)
#pragma unroll
                for (int y = 0; y < 8; y++) acc[x][y] += a[x] * b[y];
        }
        __syncthreads();
    }

    float alpha = alpha_const;
    if (alpha_ptr) alpha *= *alpha_ptr;

#pragma unroll
    for (int x = 0; x < 8; x++) {
        int gi = i0 + tr + x;
        if (gi >= M) break;
#pragma unroll
        for (int y = 0; y < 8; y++) {
            int gj = j0 + tc + y;
            if (gj >= N) continue;
            float v = alpha * acc[x][y];
            if (bias_mode == 1) v += bias[gj];
            else if (bias_mode == 2) v += bias[gi];
            if (Rm) v += Rm[(long)gi * ldr + gj];
            Cm[(long)gi * ldc + gj] = v;
        }
    }
}

// ---------------- row softmax over 2304 columns (256 thr * 9 elems) ----------------
__global__ void softmax2304(float* __restrict__ x)
{
    long row = blockIdx.x;
    float* p = x + row * (long)HWN;
    int t = threadIdx.x;
    float v[9];
    float mx = -1e30f;
#pragma unroll
    for (int i = 0; i < 9; i++) { v[i] = p[t + 256 * i]; mx = fmaxf(mx, v[i]); }

    __shared__ float red[256];
    red[t] = mx; __syncthreads();
    for (int s = 128; s > 0; s >>= 1) { if (t < s) red[t] = fmaxf(red[t], red[t + s]); __syncthreads(); }
    mx = red[0]; __syncthreads();

    float sm = 0.f;
#pragma unroll
    for (int i = 0; i < 9; i++) { v[i] = expf(v[i] - mx); sm += v[i]; }
    red[t] = sm; __syncthreads();
    for (int s = 128; s > 0; s >>= 1) { if (t < s) red[t] += red[t + s]; __syncthreads(); }
    float inv = 1.f / red[0];
#pragma unroll
    for (int i = 0; i < 9; i++) p[t + 256 * i] = v[i] * inv;
}

// ---------------- masked pooling: proto[b,c] = sum_n mid2[b,n,c]*m[b,n] / (sum m + 1e-5) ------
__global__ void proto_partial(const float* __restrict__ mid2, const float* __restrict__ mask,
                              float* __restrict__ pp, float* __restrict__ pm)
{
    int b = blockIdx.y, chunk = blockIdx.x;  // 18 chunks of 128 rows
    int c = threadIdx.x;                     // 512
    const float* mp = mask + (long)b * HWN + chunk * 128;
    const float* xp = mid2 + (long)b * HWN * CC + (long)chunk * 128 * CC + c;
    float acc = 0.f, ms = 0.f;
    for (int n = 0; n < 128; n++) {
        float m = mp[n];
        ms += m;
        acc += xp[(long)n * CC] * m;
    }
    pp[((long)b * 18 + chunk) * CC + c] = acc;
    if (c == 0) pm[b * 18 + chunk] = ms;
}

__global__ void proto_reduce(const float* __restrict__ pp, const float* __restrict__ pm,
                             float* __restrict__ proto)
{
    int b = blockIdx.x, c = threadIdx.x;
    float acc = 0.f, ms = 0.f;
    for (int k = 0; k < 18; k++) {
        acc += pp[((long)b * 18 + k) * CC + c];
        ms  += pm[b * 18 + k];
    }
    proto[b * CC + c] = acc / (ms + 1e-5f);
}

// ---------------- pf projections: qp/kp/vp[b,c2] = proto[b,:]·W[c2,:] + bias[c2] -------------
__global__ void pf_gemv(const float* __restrict__ proto,
                        const float* __restrict__ wq, const float* __restrict__ bq,
                        const float* __restrict__ wk, const float* __restrict__ bk,
                        const float* __restrict__ wv, const float* __restrict__ bv,
                        float* __restrict__ qp, float* __restrict__ kp, float* __restrict__ vp)
{
    int b = blockIdx.z, which = blockIdx.y;
    const float* W    = (which == 0) ? wq : (which == 1) ? wk : wv;
    const float* bias = (which == 0) ? bq : (which == 1) ? bk : bv;
    float* out        = (which == 0) ? qp : (which == 1) ? kp : vp;
    int warp = threadIdx.x >> 5, lane = threadIdx.x & 31;
    int c2 = blockIdx.x * 8 + warp;
    const float* pr = proto + b * CC;
    const float* wr = W + (long)c2 * CC;
    float acc = 0.f;
    for (int c = lane; c < CC; c += 32) acc += pr[c] * wr[c];
#pragma unroll
    for (int o = 16; o > 0; o >>= 1) acc += __shfl_xor_sync(0xFFFFFFFFu, acc, o);
    if (lane == 0) out[b * CC + c2] = acc + bias[c2];
}

__global__ void aw_kernel(const float* __restrict__ qp, const float* __restrict__ kp,
                          float* __restrict__ aw)
{
    int b = blockIdx.x, t = threadIdx.x;
    float acc = 0.f;
    for (int c = t; c < CC; c += 256) acc += qp[b * CC + c] * kp[b * CC + c];
    __shared__ float red[256];
    red[t] = acc; __syncthreads();
    for (int s = 128; s > 0; s >>= 1) { if (t < s) red[t] += red[t + s]; __syncthreads(); }
    if (t == 0) aw[b] = red[0];
}

// final: softmax over batch axis of aw, weighted sum of vp -> out[512]
__global__ void final_kernel(const float* __restrict__ aw, const float* __restrict__ vp,
                             float* __restrict__ out, int out_size)
{
    int c = threadIdx.x;  // 512
    float a[BB];
    float mx = -1e30f;
#pragma unroll
    for (int b = 0; b < BB; b++) { a[b] = aw[b]; mx = fmaxf(mx, a[b]); }
    float s = 0.f;
#pragma unroll
    for (int b = 0; b < BB; b++) { a[b] = expf(a[b] - mx); s += a[b]; }
    float inv = 1.f / s;
    float f = 0.f;
#pragma unroll
    for (int b = 0; b < BB; b++) f += a[b] * inv * vp[b * CC + c];
    if (c < out_size) out[c] = f;
}

// ---------------------------------------------------------------------------------------------
extern "C" void kernel_launch(void* const* d_in, const int* in_sizes, int n_in,
                              void* d_out, int out_size)
{
    const float* qry   = (const float*)d_in[0];
    const float* spt   = (const float*)d_in[1];
    const float* mask  = (const float*)d_in[2];
    const float* w_wq  = (const float*)d_in[3];
    const float* b_wq  = (const float*)d_in[4];
    const float* w_wk  = (const float*)d_in[5];
    const float* b_wk  = (const float*)d_in[6];
    const float* w_wv1 = (const float*)d_in[7];
    const float* b_wv1 = (const float*)d_in[8];
    const float* w_wv2 = (const float*)d_in[9];
    const float* b_wv2 = (const float*)d_in[10];
    const float* gamma1 = (const float*)d_in[11];
    const float* gamma2 = (const float*)d_in[12];
    const float* ca_wq = (const float*)d_in[13];
    const float* ca_bq = (const float*)d_in[14];
    const float* ca_wk = (const float*)d_in[15];
    const float* ca_bk = (const float*)d_in[16];
    const float* ca_wv = (const float*)d_in[17];
    const float* ca_bv = (const float*)d_in[18];
    const float* ca_wo = (const float*)d_in[19];
    const float* ca_bo = (const float*)d_in[20];
    const float* pf_wq = (const float*)d_in[21];
    const float* pf_bq = (const float*)d_in[22];
    const float* pf_wk = (const float*)d_in[23];
    const float* pf_bk = (const float*)d_in[24];
    const float* pf_wv = (const float*)d_in[25];
    const float* pf_bv = (const float*)d_in[26];

    float *p_q, *p_kt, *p_attn, *p_v1, *p_v2, *p_x1, *p_x2, *p_q2, *p_k2, *p_v2f;
    float *p_mid, *p_mid2, *p_pp, *p_pm, *p_proto, *p_qp, *p_kp, *p_vp, *p_aw;
    cudaGetSymbolAddress((void**)&p_q, g_q);
    cudaGetSymbolAddress((void**)&p_kt, g_kt);
    cudaGetSymbolAddress((void**)&p_attn, g_attn);
    cudaGetSymbolAddress((void**)&p_v1, g_v1);
    cudaGetSymbolAddress((void**)&p_v2, g_v2);
    cudaGetSymbolAddress((void**)&p_x1, g_x1);
    cudaGetSymbolAddress((void**)&p_x2, g_x2);
    cudaGetSymbolAddress((void**)&p_q2, g_q2);
    cudaGetSymbolAddress((void**)&p_k2, g_k2);
    cudaGetSymbolAddress((void**)&p_v2f, g_v2f);
    cudaGetSymbolAddress((void**)&p_mid, g_mid);
    cudaGetSymbolAddress((void**)&p_mid2, g_mid2);
    cudaGetSymbolAddress((void**)&p_pp, g_pp);
    cudaGetSymbolAddress((void**)&p_pm, g_pm);
    cudaGetSymbolAddress((void**)&p_proto, g_proto);
    cudaGetSymbolAddress((void**)&p_qp, g_qp);
    cudaGetSymbolAddress((void**)&p_kp, g_kp);
    cudaGetSymbolAddress((void**)&p_vp, g_vp);
    cudaGetSymbolAddress((void**)&p_aw, g_aw);

    const long CHW  = (long)CC * HWN;
    const long HWD  = (long)HWN * DD;
    const long HWHW = (long)HWN * HWN;
    dim3 blk(256);

    // 1) q[b,n,d] = qry^T @ w_wq^T + b_wq      (M=2304, N=64, K=512)
    sgemm_kernel<<<dim3(1, 18, BB), blk>>>(HWN, DD, CC,
        qry, 1, HWN, CHW,  w_wq, 1, CC, 0,
        p_q, DD, HWD,  b_wq, 1,  nullptr, 1.f,  nullptr, 0, 0);
    // 2) kt[b,m,d] = spt^T @ w_wk^T + b_wk
    sgemm_kernel<<<dim3(1, 18, BB), blk>>>(HWN, DD, CC,
        spt, 1, HWN, CHW,  w_wk, 1, CC, 0,
        p_kt, DD, HWD,  b_wk, 1,  nullptr, 1.f,  nullptr, 0, 0);
    // 3) attn[n,m] = q[n,:]·kt[m,:]            (M=N=2304, K=64)
    sgemm_kernel<<<dim3(18, 18, BB), blk>>>(HWN, HWN, DD,
        p_q, DD, 1, HWD,  p_kt, 1, DD, HWD,
        p_attn, HWN, HWHW,  nullptr, 0,  nullptr, 1.f,  nullptr, 0, 0);
    // 4) softmax rows
    softmax2304<<<BB * HWN, 256>>>(p_attn);
    // 5) v1 = w_wv1 @ qry + b_wv1 (per-row bias)   (M=512, N=2304, K=512)
    sgemm_kernel<<<dim3(18, 4, BB), blk>>>(CC, HWN, CC,
        w_wv1, CC, 1, 0,  qry, HWN, 1, CHW,
        p_v1, HWN, CHW,  b_wv1, 2,  nullptr, 1.f,  nullptr, 0, 0);
    // 6) v2 = w_wv2 @ spt + b_wv2
    sgemm_kernel<<<dim3(18, 4, BB), blk>>>(CC, HWN, CC,
        w_wv2, CC, 1, 0,  spt, HWN, 1, CHW,
        p_v2, HWN, CHW,  b_wv2, 2,  nullptr, 1.f,  nullptr, 0, 0);
    // 7) x1[c,m] = gamma1 * sum_n v1[c,n]*attn[m,n] + qry[c,m]   (M=512, N=2304, K=2304)
    sgemm_kernel<<<dim3(18, 4, BB), blk>>>(CC, HWN, HWN,
        p_v1, HWN, 1, CHW,  p_attn, 1, HWN, HWHW,
        p_x1, HWN, CHW,  nullptr, 0,  gamma1, 1.f,  qry, HWN, CHW);
    // 8) x2[c,m] = gamma2 * sum_n v2[c,n]*attn[n,m] + spt[c,m]
    sgemm_kernel<<<dim3(18, 4, BB), blk>>>(CC, HWN, HWN,
        p_v2, HWN, 1, CHW,  p_attn, HWN, 1, HWHW,
        p_x2, HWN, CHW,  nullptr, 0,  gamma2, 1.f,  spt, HWN, CHW);
    // 9) q2[n,j] = x1^T @ ca_wq^T + ca_bq      (M=2304, N=512, K=512)
    sgemm_kernel<<<dim3(4, 18, BB), blk>>>(HWN, CC, CC,
        p_x1, 1, HWN, CHW,  ca_wq, 1, CC, 0,
        p_q2, CC, CHW,  ca_bq, 1,  nullptr, 1.f,  nullptr, 0, 0);
    // 10) k2
    sgemm_kernel<<<dim3(4, 18, BB), blk>>>(HWN, CC, CC,
        p_x2, 1, HWN, CHW,  ca_wk, 1, CC, 0,
        p_k2, CC, CHW,  ca_bk, 1,  nullptr, 1.f,  nullptr, 0, 0);
    // 11) v2f
    sgemm_kernel<<<dim3(4, 18, BB), blk>>>(HWN, CC, CC,
        p_x2, 1, HWN, CHW,  ca_wv, 1, CC, 0,
        p_v2f, CC, CHW,  ca_bv, 1,  nullptr, 1.f,  nullptr, 0, 0);
    // 12) scores[n,m] = q2[n,:]·k2[m,:] / sqrt(512)   (M=N=2304, K=512) -> reuse g_attn
    sgemm_kernel<<<dim3(18, 18, BB), blk>>>(HWN, HWN, CC,
        p_q2, CC, 1, CHW,  p_k2, 1, CC, CHW,
        p_attn, HWN, HWHW,  nullptr, 0,  nullptr, 0.044194173824159216f,  nullptr, 0, 0);
    // 13) softmax rows
    softmax2304<<<BB * HWN, 256>>>(p_attn);
    // 14) mid[n,c] = sum_m attn2[n,m]*v2f[m,c]   (M=2304, N=512, K=2304)
    sgemm_kernel<<<dim3(4, 18, BB), blk>>>(HWN, CC, HWN,
        p_attn, HWN, 1, HWHW,  p_v2f, CC, 1, CHW,
        p_mid, CC, CHW,  nullptr, 0,  nullptr, 1.f,  nullptr, 0, 0);
    // 15) mid2 = mid @ ca_wo^T + ca_bo
    sgemm_kernel<<<dim3(4, 18, BB), blk>>>(HWN, CC, CC,
        p_mid, CC, 1, CHW,  ca_wo, 1, CC, 0,
        p_mid2, CC, CHW,  ca_bo, 1,  nullptr, 1.f,  nullptr, 0, 0);
    // 16) masked pooling -> proto
    proto_partial<<<dim3(18, BB), 512>>>(p_mid2, mask, p_pp, p_pm);
    proto_reduce<<<BB, 512>>>(p_pp, p_pm, p_proto);
    // 17) pf projections
    pf_gemv<<<dim3(CC / 8, 3, BB), 256>>>(p_proto,
        pf_wq, pf_bq, pf_wk, pf_bk, pf_wv, pf_bv, p_qp, p_kp, p_vp);
    // 18) aw[b] = qp[b]·kp[b]
    aw_kernel<<<BB, 256>>>(p_qp, p_kp, p_aw);
    // 19) softmax over batch + weighted sum -> out
    final_kernel<<<1, 512>>>(p_aw, p_vp, (float*)d_out, out_size);
}

// round 3
// speedup vs baseline: 1.9227x; 1.9227x over previous
#include <cuda_runtime.h>
#include <math.h>
#include <stdint.h>

#define BB 8
#define CC 512
#define DD 64
#define HWN 2304  // 48*48

// ---------------- scratch (static device globals; no allocation) ----------------
__device__ float g_q  [(size_t)BB*HWN*DD];
__device__ float g_kt [(size_t)BB*HWN*DD];
__device__ float g_attn[(size_t)BB*HWN*HWN];     // reused for scores
__device__ float g_v1 [(size_t)BB*CC*HWN];
__device__ float g_v2 [(size_t)BB*CC*HWN];
__device__ float g_x1 [(size_t)BB*CC*HWN];
__device__ float g_x2 [(size_t)BB*CC*HWN];
__device__ float g_q2 [(size_t)BB*HWN*CC];
__device__ float g_k2 [(size_t)BB*HWN*CC];
__device__ float g_v2f[(size_t)BB*HWN*CC];
__device__ float g_mid[(size_t)BB*HWN*CC];
__device__ float g_mid2[(size_t)BB*HWN*CC];
__device__ float g_pp [(size_t)BB*18*CC];
__device__ float g_pm [BB*18];
__device__ float g_proto[BB*CC];
__device__ float g_qp [BB*CC];
__device__ float g_kp [BB*CC];
__device__ float g_vp [BB*CC];
__device__ float g_aw [BB];

// ---------------- tf32 tensor-core SGEMM ------------------------------------------
// C[i,j] = alpha*sum_k A[i,k]*B[k,j] (+bias)(+res), generic strides, batched over z.
// Block tile 128x128, K-tile 32. 8 warps: 2 (M) x 4 (N), warp tile 64x32.
// mma.sync m16n8k8 tf32 with fp32 accumulate.
#define BM 128
#define BN 128
#define BK 32
#define A_PAD 36    // bank = (4*row + col) % 32 -> conflict free for frag loads
#define B_PAD 136   // bank = (8*k + n) % 32   -> conflict free for frag loads

__device__ __forceinline__ uint32_t f2tf32(float x) {
    uint32_t r;
    asm("cvt.rna.tf32.f32 %0, %1;" : "=r"(r) : "f"(x));
    return r;
}

__global__ __launch_bounds__(256, 2)
void tgemm_kernel(int M, int N, int K,
                  const float* __restrict__ A, long sa_r, long sa_c, long bsA,
                  const float* __restrict__ Bm, long sb_r, long sb_c, long bsB,
                  float* __restrict__ Cm, long ldc, long bsC,
                  const float* __restrict__ bias, int bias_mode,   // 0 none, 1 per-col(j), 2 per-row(i)
                  const float* __restrict__ alpha_ptr, float alpha_const,
                  const float* __restrict__ Rm, long ldr, long bsR)
{
    __shared__ uint32_t As[BM][A_PAD];   // [m][k] tf32 bits
    __shared__ uint32_t Bs[BK][B_PAD];   // [k][n] tf32 bits

    int bz = blockIdx.z;
    A  += (long)bz * bsA;
    Bm += (long)bz * bsB;
    Cm += (long)bz * bsC;
    if (Rm) Rm += (long)bz * bsR;

    int i0 = blockIdx.y * BM, j0 = blockIdx.x * BN;
    int tid = threadIdx.x;
    int lane = tid & 31, wid = tid >> 5;
    int warp_m = (wid & 1) * 64;
    int warp_n = (wid >> 1) * 32;
    int g = lane >> 2;        // 0..7
    int tg = lane & 3;        // 0..3

    float acc[4][4][4];       // [mt][nt][c0..c3]
#pragma unroll
    for (int a = 0; a < 4; a++)
#pragma unroll
        for (int b = 0; b < 4; b++)
#pragma unroll
            for (int c = 0; c < 4; c++) acc[a][b][c] = 0.f;

    for (int k0 = 0; k0 < K; k0 += BK) {
        // ---- load A tile into As[m][k] ----
        if (sa_c == 1) {
#pragma unroll
            for (int it = 0; it < 16; it++) {
                int idx = tid + it * 256;
                int k = idx & (BK - 1), m = idx >> 5;
                int gi = i0 + m, gk = k0 + k;
                float v = (gi < M && gk < K) ? A[(long)gi * sa_r + gk] : 0.f;
                As[m][k] = f2tf32(v);
            }
        } else {
#pragma unroll
            for (int it = 0; it < 16; it++) {
                int idx = tid + it * 256;
                int m = idx & (BM - 1), k = idx >> 7;
                int gi = i0 + m, gk = k0 + k;
                float v = (gi < M && gk < K) ? A[(long)gi + (long)gk * sa_c] : 0.f;
                As[m][k] = f2tf32(v);
            }
        }
        // ---- load B tile into Bs[k][n] ----
        if (sb_c == 1) {
#pragma unroll
            for (int it = 0; it < 16; it++) {
                int idx = tid + it * 256;
                int n = idx & (BN - 1), k = idx >> 7;
                int gj = j0 + n, gk = k0 + k;
                float v = (gj < N && gk < K) ? Bm[(long)gk * sb_r + gj] : 0.f;
                Bs[k][n] = f2tf32(v);
            }
        } else {
#pragma unroll
            for (int it = 0; it < 16; it++) {
                int idx = tid + it * 256;
                int k = idx & (BK - 1), n = idx >> 5;
                int gj = j0 + n, gk = k0 + k;
                float v = (gj < N && gk < K) ? Bm[(long)gk + (long)gj * sb_c] : 0.f;
                Bs[k][n] = f2tf32(v);
            }
        }
        __syncthreads();

#pragma unroll
        for (int ks = 0; ks < 4; ks++) {
            int kb = ks * 8;
            uint32_t a[4][4];
#pragma unroll
            for (int mt = 0; mt < 4; mt++) {
                int r = warp_m + mt * 16 + g;
                a[mt][0] = As[r][kb + tg];
                a[mt][1] = As[r + 8][kb + tg];
                a[mt][2] = As[r][kb + tg + 4];
                a[mt][3] = As[r + 8][kb + tg + 4];
            }
            uint32_t b[4][2];
#pragma unroll
            for (int nt = 0; nt < 4; nt++) {
                int cidx = warp_n + nt * 8 + g;
                b[nt][0] = Bs[kb + tg][cidx];
                b[nt][1] = Bs[kb + tg + 4][cidx];
            }
#pragma unroll
            for (int mt = 0; mt < 4; mt++)
#pragma unroll
                for (int nt = 0; nt < 4; nt++) {
                    asm volatile(
                        "mma.sync.aligned.m16n8k8.row.col.f32.tf32.tf32.f32 "
                        "{%0,%1,%2,%3}, {%4,%5,%6,%7}, {%8,%9}, {%0,%1,%2,%3};\n"
                        : "+f"(acc[mt][nt][0]), "+f"(acc[mt][nt][1]),
                          "+f"(acc[mt][nt][2]), "+f"(acc[mt][nt][3])
                        : "r"(a[mt][0]), "r"(a[mt][1]), "r"(a[mt][2]), "r"(a[mt][3]),
                          "r"(b[nt][0]), "r"(b[nt][1]));
                }
        }
        __syncthreads();
    }

    float alpha = alpha_const;
    if (alpha_ptr) alpha *= *alpha_ptr;

#pragma unroll
    for (int mt = 0; mt < 4; mt++) {
#pragma unroll
        for (int nt = 0; nt < 4; nt++) {
#pragma unroll
            for (int c = 0; c < 4; c++) {
                int gi = i0 + warp_m + mt * 16 + g + (c >= 2 ? 8 : 0);
                int gj = j0 + warp_n + nt * 8 + tg * 2 + (c & 1);
                if (gi >= M || gj >= N) continue;
                float v = alpha * acc[mt][nt][c];
                if (bias_mode == 1) v += bias[gj];
                else if (bias_mode == 2) v += bias[gi];
                if (Rm) v += Rm[(long)gi * ldr + gj];
                Cm[(long)gi * ldc + gj] = v;
            }
        }
    }
}

// ---------------- row softmax over 2304 columns (256 thr * 9 elems) ----------------
__global__ void softmax2304(float* __restrict__ x)
{
    long row = blockIdx.x;
    float* p = x + row * (long)HWN;
    int t = threadIdx.x;
    float v[9];
    float mx = -1e30f;
#pragma unroll
    for (int i = 0; i < 9; i++) { v[i] = p[t + 256 * i]; mx = fmaxf(mx, v[i]); }

    __shared__ float red[256];
    red[t] = mx; __syncthreads();
    for (int s = 128; s > 0; s >>= 1) { if (t < s) red[t] = fmaxf(red[t], red[t + s]); __syncthreads(); }
    mx = red[0]; __syncthreads();

    float sm = 0.f;
#pragma unroll
    for (int i = 0; i < 9; i++) { v[i] = expf(v[i] - mx); sm += v[i]; }
    red[t] = sm; __syncthreads();
    for (int s = 128; s > 0; s >>= 1) { if (t < s) red[t] += red[t + s]; __syncthreads(); }
    float inv = 1.f / red[0];
#pragma unroll
    for (int i = 0; i < 9; i++) p[t + 256 * i] = v[i] * inv;
}

// ---------------- masked pooling: proto[b,c] = sum_n mid2[b,n,c]*m[b,n] / (sum m + 1e-5) ------
__global__ void proto_partial(const float* __restrict__ mid2, const float* __restrict__ mask,
                              float* __restrict__ pp, float* __restrict__ pm)
{
    int b = blockIdx.y, chunk = blockIdx.x;  // 18 chunks of 128 rows
    int c = threadIdx.x;                     // 512
    const float* mp = mask + (long)b * HWN + chunk * 128;
    const float* xp = mid2 + (long)b * HWN * CC + (long)chunk * 128 * CC + c;
    float acc = 0.f, ms = 0.f;
    for (int n = 0; n < 128; n++) {
        float m = mp[n];
        ms += m;
        acc += xp[(long)n * CC] * m;
    }
    pp[((long)b * 18 + chunk) * CC + c] = acc;
    if (c == 0) pm[b * 18 + chunk] = ms;
}

__global__ void proto_reduce(const float* __restrict__ pp, const float* __restrict__ pm,
                             float* __restrict__ proto)
{
    int b = blockIdx.x, c = threadIdx.x;
    float acc = 0.f, ms = 0.f;
    for (int k = 0; k < 18; k++) {
        acc += pp[((long)b * 18 + k) * CC + c];
        ms  += pm[b * 18 + k];
    }
    proto[b * CC + c] = acc / (ms + 1e-5f);
}

// ---------------- pf projections: qp/kp/vp[b,c2] = proto[b,:]·W[c2,:] + bias[c2] -------------
__global__ void pf_gemv(const float* __restrict__ proto,
                        const float* __restrict__ wq, const float* __restrict__ bq,
                        const float* __restrict__ wk, const float* __restrict__ bk,
                        const float* __restrict__ wv, const float* __restrict__ bv,
                        float* __restrict__ qp, float* __restrict__ kp, float* __restrict__ vp)
{
    int b = blockIdx.z, which = blockIdx.y;
    const float* W    = (which == 0) ? wq : (which == 1) ? wk : wv;
    const float* bias = (which == 0) ? bq : (which == 1) ? bk : bv;
    float* out        = (which == 0) ? qp : (which == 1) ? kp : vp;
    int warp = threadIdx.x >> 5, lane = threadIdx.x & 31;
    int c2 = blockIdx.x * 8 + warp;
    const float* pr = proto + b * CC;
    const float* wr = W + (long)c2 * CC;
    float acc = 0.f;
    for (int c = lane; c < CC; c += 32) acc += pr[c] * wr[c];
#pragma unroll
    for (int o = 16; o > 0; o >>= 1) acc += __shfl_xor_sync(0xFFFFFFFFu, acc, o);
    if (lane == 0) out[b * CC + c2] = acc + bias[c2];
}

__global__ void aw_kernel(const float* __restrict__ qp, const float* __restrict__ kp,
                          float* __restrict__ aw)
{
    int b = blockIdx.x, t = threadIdx.x;
    float acc = 0.f;
    for (int c = t; c < CC; c += 256) acc += qp[b * CC + c] * kp[b * CC + c];
    __shared__ float red[256];
    red[t] = acc; __syncthreads();
    for (int s = 128; s > 0; s >>= 1) { if (t < s) red[t] += red[t + s]; __syncthreads(); }
    if (t == 0) aw[b] = red[0];
}

// final: softmax over batch axis of aw, weighted sum of vp -> out[512]
__global__ void final_kernel(const float* __restrict__ aw, const float* __restrict__ vp,
                             float* __restrict__ out, int out_size)
{
    int c = threadIdx.x;  // 512
    float a[BB];
    float mx = -1e30f;
#pragma unroll
    for (int b = 0; b < BB; b++) { a[b] = aw[b]; mx = fmaxf(mx, a[b]); }
    float s = 0.f;
#pragma unroll
    for (int b = 0; b < BB; b++) { a[b] = expf(a[b] - mx); s += a[b]; }
    float inv = 1.f / s;
    float f = 0.f;
#pragma unroll
    for (int b = 0; b < BB; b++) f += a[b] * inv * vp[b * CC + c];
    if (c < out_size) out[c] = f;
}

// ---------------------------------------------------------------------------------------------
extern "C" void kernel_launch(void* const* d_in, const int* in_sizes, int n_in,
                              void* d_out, int out_size)
{
    const float* qry   = (const float*)d_in[0];
    const float* spt   = (const float*)d_in[1];
    const float* mask  = (const float*)d_in[2];
    const float* w_wq  = (const float*)d_in[3];
    const float* b_wq  = (const float*)d_in[4];
    const float* w_wk  = (const float*)d_in[5];
    const float* b_wk  = (const float*)d_in[6];
    const float* w_wv1 = (const float*)d_in[7];
    const float* b_wv1 = (const float*)d_in[8];
    const float* w_wv2 = (const float*)d_in[9];
    const float* b_wv2 = (const float*)d_in[10];
    const float* gamma1 = (const float*)d_in[11];
    const float* gamma2 = (const float*)d_in[12];
    const float* ca_wq = (const float*)d_in[13];
    const float* ca_bq = (const float*)d_in[14];
    const float* ca_wk = (const float*)d_in[15];
    const float* ca_bk = (const float*)d_in[16];
    const float* ca_wv = (const float*)d_in[17];
    const float* ca_bv = (const float*)d_in[18];
    const float* ca_wo = (const float*)d_in[19];
    const float* ca_bo = (const float*)d_in[20];
    const float* pf_wq = (const float*)d_in[21];
    const float* pf_bq = (const float*)d_in[22];
    const float* pf_wk = (const float*)d_in[23];
    const float* pf_bk = (const float*)d_in[24];
    const float* pf_wv = (const float*)d_in[25];
    const float* pf_bv = (const float*)d_in[26];

    float *p_q, *p_kt, *p_attn, *p_v1, *p_v2, *p_x1, *p_x2, *p_q2, *p_k2, *p_v2f;
    float *p_mid, *p_mid2, *p_pp, *p_pm, *p_proto, *p_qp, *p_kp, *p_vp, *p_aw;
    cudaGetSymbolAddress((void**)&p_q, g_q);
    cudaGetSymbolAddress((void**)&p_kt, g_kt);
    cudaGetSymbolAddress((void**)&p_attn, g_attn);
    cudaGetSymbolAddress((void**)&p_v1, g_v1);
    cudaGetSymbolAddress((void**)&p_v2, g_v2);
    cudaGetSymbolAddress((void**)&p_x1, g_x1);
    cudaGetSymbolAddress((void**)&p_x2, g_x2);
    cudaGetSymbolAddress((void**)&p_q2, g_q2);
    cudaGetSymbolAddress((void**)&p_k2, g_k2);
    cudaGetSymbolAddress((void**)&p_v2f, g_v2f);
    cudaGetSymbolAddress((void**)&p_mid, g_mid);
    cudaGetSymbolAddress((void**)&p_mid2, g_mid2);
    cudaGetSymbolAddress((void**)&p_pp, g_pp);
    cudaGetSymbolAddress((void**)&p_pm, g_pm);
    cudaGetSymbolAddress((void**)&p_proto, g_proto);
    cudaGetSymbolAddress((void**)&p_qp, g_qp);
    cudaGetSymbolAddress((void**)&p_kp, g_kp);
    cudaGetSymbolAddress((void**)&p_vp, g_vp);
    cudaGetSymbolAddress((void**)&p_aw, g_aw);

    const long CHW  = (long)CC * HWN;
    const long HWD  = (long)HWN * DD;
    const long HWHW = (long)HWN * HWN;
    dim3 blk(256);

    // 1) q[b,n,d] = qry^T @ w_wq^T + b_wq      (M=2304, N=64, K=512)
    tgemm_kernel<<<dim3(1, 18, BB), blk>>>(HWN, DD, CC,
        qry, 1, HWN, CHW,  w_wq, 1, CC, 0,
        p_q, DD, HWD,  b_wq, 1,  nullptr, 1.f,  nullptr, 0, 0);
    // 2) kt[b,m,d] = spt^T @ w_wk^T + b_wk
    tgemm_kernel<<<dim3(1, 18, BB), blk>>>(HWN, DD, CC,
        spt, 1, HWN, CHW,  w_wk, 1, CC, 0,
        p_kt, DD, HWD,  b_wk, 1,  nullptr, 1.f,  nullptr, 0, 0);
    // 3) attn[n,m] = q[n,:]·kt[m,:]            (M=N=2304, K=64)
    tgemm_kernel<<<dim3(18, 18, BB), blk>>>(HWN, HWN, DD,
        p_q, DD, 1, HWD,  p_kt, 1, DD, HWD,
        p_attn, HWN, HWHW,  nullptr, 0,  nullptr, 1.f,  nullptr, 0, 0);
    // 4) softmax rows
    softmax2304<<<BB * HWN, 256>>>(p_attn);
    // 5) v1 = w_wv1 @ qry + b_wv1 (per-row bias)   (M=512, N=2304, K=512)
    tgemm_kernel<<<dim3(18, 4, BB), blk>>>(CC, HWN, CC,
        w_wv1, CC, 1, 0,  qry, HWN, 1, CHW,
        p_v1, HWN, CHW,  b_wv1, 2,  nullptr, 1.f,  nullptr, 0, 0);
    // 6) v2 = w_wv2 @ spt + b_wv2
    tgemm_kernel<<<dim3(18, 4, BB), blk>>>(CC, HWN, CC,
        w_wv2, CC, 1, 0,  spt, HWN, 1, CHW,
        p_v2, HWN, CHW,  b_wv2, 2,  nullptr, 1.f,  nullptr, 0, 0);
    // 7) x1[c,m] = gamma1 * sum_n v1[c,n]*attn[m,n] + qry[c,m]   (M=512, N=2304, K=2304)
    tgemm_kernel<<<dim3(18, 4, BB), blk>>>(CC, HWN, HWN,
        p_v1, HWN, 1, CHW,  p_attn, 1, HWN, HWHW,
        p_x1, HWN, CHW,  nullptr, 0,  gamma1, 1.f,  qry, HWN, CHW);
    // 8) x2[c,m] = gamma2 * sum_n v2[c,n]*attn[n,m] + spt[c,m]
    tgemm_kernel<<<dim3(18, 4, BB), blk>>>(CC, HWN, HWN,
        p_v2, HWN, 1, CHW,  p_attn, HWN, 1, HWHW,
        p_x2, HWN, CHW,  nullptr, 0,  gamma2, 1.f,  spt, HWN, CHW);
    // 9) q2[n,j] = x1^T @ ca_wq^T + ca_bq      (M=2304, N=512, K=512)
    tgemm_kernel<<<dim3(4, 18, BB), blk>>>(HWN, CC, CC,
        p_x1, 1, HWN, CHW,  ca_wq, 1, CC, 0,
        p_q2, CC, CHW,  ca_bq, 1,  nullptr, 1.f,  nullptr, 0, 0);
    // 10) k2
    tgemm_kernel<<<dim3(4, 18, BB), blk>>>(HWN, CC, CC,
        p_x2, 1, HWN, CHW,  ca_wk, 1, CC, 0,
        p_k2, CC, CHW,  ca_bk, 1,  nullptr, 1.f,  nullptr, 0, 0);
    // 11) v2f
    tgemm_kernel<<<dim3(4, 18, BB), blk>>>(HWN, CC, CC,
        p_x2, 1, HWN, CHW,  ca_wv, 1, CC, 0,
        p_v2f, CC, CHW,  ca_bv, 1,  nullptr, 1.f,  nullptr, 0, 0);
    // 12) scores[n,m] = q2[n,:]·k2[m,:] / sqrt(512)   (M=N=2304, K=512) -> reuse g_attn
    tgemm_kernel<<<dim3(18, 18, BB), blk>>>(HWN, HWN, CC,
        p_q2, CC, 1, CHW,  p_k2, 1, CC, CHW,
        p_attn, HWN, HWHW,  nullptr, 0,  nullptr, 0.044194173824159216f,  nullptr, 0, 0);
    // 13) softmax rows
    softmax2304<<<BB * HWN, 256>>>(p_attn);
    // 14) mid[n,c] = sum_m attn2[n,m]*v2f[m,c]   (M=2304, N=512, K=2304)
    tgemm_kernel<<<dim3(4, 18, BB), blk>>>(HWN, CC, HWN,
        p_attn, HWN, 1, HWHW,  p_v2f, CC, 1, CHW,
        p_mid, CC, CHW,  nullptr, 0,  nullptr, 1.f,  nullptr, 0, 0);
    // 15) mid2 = mid @ ca_wo^T + ca_bo
    tgemm_kernel<<<dim3(4, 18, BB), blk>>>(HWN, CC, CC,
        p_mid, CC, 1, CHW,  ca_wo, 1, CC, 0,
        p_mid2, CC, CHW,  ca_bo, 1,  nullptr, 1.f,  nullptr, 0, 0);
    // 16) masked pooling -> proto
    proto_partial<<<dim3(18, BB), 512>>>(p_mid2, mask, p_pp, p_pm);
    proto_reduce<<<BB, 512>>>(p_pp, p_pm, p_proto);
    // 17) pf projections
    pf_gemv<<<dim3(CC / 8, 3, BB), 256>>>(p_proto,
        pf_wq, pf_bq, pf_wk, pf_bk, pf_wv, pf_bv, p_qp, p_kp, p_vp);
    // 18) aw[b] = qp[b]·kp[b]
    aw_kernel<<<BB, 256>>>(p_qp, p_kp, p_aw);
    // 19) softmax over batch + weighted sum -> out
    final_kernel<<<1, 512>>>(p_aw, p_vp, (float*)d_out, out_size);
}

// round 7
// speedup vs baseline: 3.8835x; 2.0198x over previous
#include <cuda_runtime.h>
#include <cuda_fp16.h>
#include <math.h>
#include <stdint.h>

#define BB 8
#define CC 512
#define DD 64
#define HWN 2304  // 48*48

// ---------------- scratch (static device globals; no allocation) ----------------
__device__ float g_q  [(size_t)BB*HWN*DD];
__device__ float g_kt [(size_t)BB*HWN*DD];
__device__ float g_attn[(size_t)BB*HWN*HWN];     // reused for scores
__device__ float g_v1 [(size_t)BB*CC*HWN];
__device__ float g_v2 [(size_t)BB*CC*HWN];
__device__ float g_x1 [(size_t)BB*CC*HWN];
__device__ float g_x2 [(size_t)BB*CC*HWN];
__device__ float g_q2 [(size_t)BB*HWN*CC];
__device__ float g_k2 [(size_t)BB*HWN*CC];
__device__ float g_v2f[(size_t)BB*HWN*CC];
__device__ float g_mid[(size_t)BB*HWN*CC];
__device__ float g_mid2[(size_t)BB*HWN*CC];
__device__ float g_pp [(size_t)BB*18*CC];
__device__ float g_pm [BB*18];
__device__ float g_proto[BB*CC];
__device__ float g_qp [BB*CC];
__device__ float g_kp [BB*CC];
__device__ float g_vp [BB*CC];
__device__ float g_aw [BB];

// ---------------- fp16 tensor-core GEMM (mma.sync m16n8k16, f32 accum) ------------
// C[i,j] = alpha*sum_k A[i,k]*B[k,j] (+bias)(+res), generic strides, batched over z.
// Block tile 128x128, K-tile 32. 8 warps: 2 (M) x 4 (N), warp tile 64x32.
#define BM 128
#define BN 128
#define BK 32
#define APAD 8   // row stride 40 halves = 80B; 20*r mod 32 distinct for r=0..7

__device__ __forceinline__ uint32_t packh2(float x, float y) {
    __half2 h = __floats2half2_rn(x, y);
    return *(uint32_t*)&h;
}

__global__ __launch_bounds__(256, 2)
void hgemm_kernel(int M, int N, int K,
                  const float* __restrict__ A, long sa_r, long sa_c, long bsA,
                  const float* __restrict__ Bm, long sb_r, long sb_c, long bsB,
                  float* __restrict__ Cm, long ldc, long bsC,
                  const float* __restrict__ bias, int bias_mode,   // 0 none, 1 per-col(j), 2 per-row(i)
                  const float* __restrict__ alpha_ptr, float alpha_const,
                  const float* __restrict__ Rm, long ldr, long bsR)
{
    __shared__ __half As[BM][BK + APAD];   // [m][k]
    __shared__ __half Bs[BN][BK + APAD];   // [n][k]

    int bz = blockIdx.z;
    A  += (long)bz * bsA;
    Bm += (long)bz * bsB;
    Cm += (long)bz * bsC;
    if (Rm) Rm += (long)bz * bsR;

    int i0 = blockIdx.y * BM, j0 = blockIdx.x * BN;
    int tid = threadIdx.x;
    int lane = tid & 31, wid = tid >> 5;
    int warp_m = (wid & 1) * 64;
    int warp_n = (wid >> 1) * 32;
    int g = lane >> 2;        // 0..7
    int tg = lane & 3;        // 0..3

    float acc[4][4][4];       // [mt][nt][c0..c3]
#pragma unroll
    for (int a = 0; a < 4; a++)
#pragma unroll
        for (int b = 0; b < 4; b++)
#pragma unroll
            for (int c = 0; c < 4; c++) acc[a][b][c] = 0.f;

    for (int k0 = 0; k0 < K; k0 += BK) {
        // ---- load A tile: 128 rows x 32 k (quads of 4 k) ----
        if (sa_c == 1) {
#pragma unroll
            for (int it = 0; it < 4; it++) {
                int idx = tid + it * 256;          // 1024 quads
                int row = idx >> 3, q = idx & 7;
                const float4 f = *(const float4*)(A + (long)(i0 + row) * sa_r + k0 + q * 4);
                *(uint2*)&As[row][q * 4] = make_uint2(packh2(f.x, f.y), packh2(f.z, f.w));
            }
        } else {  // sa_r == 1
#pragma unroll
            for (int it = 0; it < 4; it++) {
                int idx = tid + it * 256;
                int row = idx & 127, q = idx >> 7;
                const float* p = A + (i0 + row) + (long)(k0 + q * 4) * sa_c;
                *(uint2*)&As[row][q * 4] =
                    make_uint2(packh2(p[0], p[sa_c]), packh2(p[2 * sa_c], p[3 * sa_c]));
            }
        }
        // ---- load B tile: 128 rows (j) x 32 k;  elem(j,k) = Bm[k*sb_r + j*sb_c] ----
        if (sb_r == 1) {
#pragma unroll
            for (int it = 0; it < 4; it++) {
                int idx = tid + it * 256;
                int row = idx >> 3, q = idx & 7;
                int gj = j0 + row;
                if (gj < N) {
                    const float4 f = *(const float4*)(Bm + (long)gj * sb_c + k0 + q * 4);
                    *(uint2*)&Bs[row][q * 4] = make_uint2(packh2(f.x, f.y), packh2(f.z, f.w));
                } else {
                    *(uint2*)&Bs[row][q * 4] = make_uint2(0u, 0u);
                }
            }
        } else {  // sb_c == 1
#pragma unroll
            for (int it = 0; it < 4; it++) {
                int idx = tid + it * 256;
                int row = idx & 127, q = idx >> 7;
                int gj = j0 + row;
                if (gj < N) {
                    const float* p = Bm + gj + (long)(k0 + q * 4) * sb_r;
                    *(uint2*)&Bs[row][q * 4] =
                        make_uint2(packh2(p[0], p[sb_r]), packh2(p[2 * sb_r], p[3 * sb_r]));
                } else {
                    *(uint2*)&Bs[row][q * 4] = make_uint2(0u, 0u);
                }
            }
        }
        __syncthreads();

#pragma unroll
        for (int ks = 0; ks < 2; ks++) {
            int kb = ks * 16;
            uint32_t a[4][4];
#pragma unroll
            for (int mt = 0; mt < 4; mt++) {
                int r = warp_m + mt * 16 + g;
                a[mt][0] = *(const uint32_t*)&As[r][kb + 2 * tg];
                a[mt][1] = *(const uint32_t*)&As[r + 8][kb + 2 * tg];
                a[mt][2] = *(const uint32_t*)&As[r][kb + 2 * tg + 8];
                a[mt][3] = *(const uint32_t*)&As[r + 8][kb + 2 * tg + 8];
            }
            uint32_t b[4][2];
#pragma unroll
            for (int nt = 0; nt < 4; nt++) {
                int cidx = warp_n + nt * 8 + g;
                b[nt][0] = *(const uint32_t*)&Bs[cidx][kb + 2 * tg];
                b[nt][1] = *(const uint32_t*)&Bs[cidx][kb + 2 * tg + 8];
            }
#pragma unroll
            for (int mt = 0; mt < 4; mt++)
#pragma unroll
                for (int nt = 0; nt < 4; nt++) {
                    asm volatile(
                        "mma.sync.aligned.m16n8k16.row.col.f32.f16.f16.f32 "
                        "{%0,%1,%2,%3}, {%4,%5,%6,%7}, {%8,%9}, {%0,%1,%2,%3};\n"
                        : "+f"(acc[mt][nt][0]), "+f"(acc[mt][nt][1]),
                          "+f"(acc[mt][nt][2]), "+f"(acc[mt][nt][3])
                        : "r"(a[mt][0]), "r"(a[mt][1]), "r"(a[mt][2]), "r"(a[mt][3]),
                          "r"(b[nt][0]), "r"(b[nt][1]));
                }
        }
        __syncthreads();
    }

    float alpha = alpha_const;
    if (alpha_ptr) alpha *= *alpha_ptr;

#pragma unroll
    for (int mt = 0; mt < 4; mt++) {
#pragma unroll
        for (int nt = 0; nt < 4; nt++) {
#pragma unroll
            for (int c = 0; c < 4; c++) {
                int gi = i0 + warp_m + mt * 16 + g + (c >= 2 ? 8 : 0);
                int gj = j0 + warp_n + nt * 8 + tg * 2 + (c & 1);
                if (gi >= M || gj >= N) continue;
                float v = alpha * acc[mt][nt][c];
                if (bias_mode == 1) v += bias[gj];
                else if (bias_mode == 2) v += bias[gi];
                if (Rm) v += Rm[(long)gi * ldr + gj];
                Cm[(long)gi * ldc + gj] = v;
            }
        }
    }
}

// ---------------- row softmax over 2304 columns (256 thr * 9 elems) ----------------
__global__ void softmax2304(float* __restrict__ x)
{
    long row = blockIdx.x;
    float* p = x + row * (long)HWN;
    int t = threadIdx.x;
    float v[9];
    float mx = -1e30f;
#pragma unroll
    for (int i = 0; i < 9; i++) { v[i] = p[t + 256 * i]; mx = fmaxf(mx, v[i]); }

    __shared__ float red[256];
    red[t] = mx; __syncthreads();
    for (int s = 128; s > 0; s >>= 1) { if (t < s) red[t] = fmaxf(red[t], red[t + s]); __syncthreads(); }
    mx = red[0]; __syncthreads();

    float sm = 0.f;
#pragma unroll
    for (int i = 0; i < 9; i++) { v[i] = expf(v[i] - mx); sm += v[i]; }
    red[t] = sm; __syncthreads();
    for (int s = 128; s > 0; s >>= 1) { if (t < s) red[t] += red[t + s]; __syncthreads(); }
    float inv = 1.f / red[0];
#pragma unroll
    for (int i = 0; i < 9; i++) p[t + 256 * i] = v[i] * inv;
}

// ---------------- masked pooling: proto[b,c] = sum_n mid2[b,n,c]*m[b,n] / (sum m + 1e-5) ------
__global__ void proto_partial(const float* __restrict__ mid2, const float* __restrict__ mask,
                              float* __restrict__ pp, float* __restrict__ pm)
{
    int b = blockIdx.y, chunk = blockIdx.x;  // 18 chunks of 128 rows
    int c = threadIdx.x;                     // 512
    const float* mp = mask + (long)b * HWN + chunk * 128;
    const float* xp = mid2 + (long)b * HWN * CC + (long)chunk * 128 * CC + c;
    float acc = 0.f, ms = 0.f;
    for (int n = 0; n < 128; n++) {
        float m = mp[n];
        ms += m;
        acc += xp[(long)n * CC] * m;
    }
    pp[((long)b * 18 + chunk) * CC + c] = acc;
    if (c == 0) pm[b * 18 + chunk] = ms;
}

__global__ void proto_reduce(const float* __restrict__ pp, const float* __restrict__ pm,
                             float* __restrict__ proto)
{
    int b = blockIdx.x, c = threadIdx.x;
    float acc = 0.f, ms = 0.f;
    for (int k = 0; k < 18; k++) {
        acc += pp[((long)b * 18 + k) * CC + c];
        ms  += pm[b * 18 + k];
    }
    proto[b * CC + c] = acc / (ms + 1e-5f);
}

// ---------------- pf projections: qp/kp/vp[b,c2] = proto[b,:]·W[c2,:] + bias[c2] -------------
__global__ void pf_gemv(const float* __restrict__ proto,
                        const float* __restrict__ wq, const float* __restrict__ bq,
                        const float* __restrict__ wk, const float* __restrict__ bk,
                        const float* __restrict__ wv, const float* __restrict__ bv,
                        float* __restrict__ qp, float* __restrict__ kp, float* __restrict__ vp)
{
    int b = blockIdx.z, which = blockIdx.y;
    const float* W    = (which == 0) ? wq : (which == 1) ? wk : wv;
    const float* bias = (which == 0) ? bq : (which == 1) ? bk : bv;
    float* out        = (which == 0) ? qp : (which == 1) ? kp : vp;
    int warp = threadIdx.x >> 5, lane = threadIdx.x & 31;
    int c2 = blockIdx.x * 8 + warp;
    const float* pr = proto + b * CC;
    const float* wr = W + (long)c2 * CC;
    float acc = 0.f;
    for (int c = lane; c < CC; c += 32) acc += pr[c] * wr[c];
#pragma unroll
    for (int o = 16; o > 0; o >>= 1) acc += __shfl_xor_sync(0xFFFFFFFFu, acc, o);
    if (lane == 0) out[b * CC + c2] = acc + bias[c2];
}

__global__ void aw_kernel(const float* __restrict__ qp, const float* __restrict__ kp,
                          float* __restrict__ aw)
{
    int b = blockIdx.x, t = threadIdx.x;
    float acc = 0.f;
    for (int c = t; c < CC; c += 256) acc += qp[b * CC + c] * kp[b * CC + c];
    __shared__ float red[256];
    red[t] = acc; __syncthreads();
    for (int s = 128; s > 0; s >>= 1) { if (t < s) red[t] += red[t + s]; __syncthreads(); }
    if (t == 0) aw[b] = red[0];
}

// final: softmax over batch axis of aw, weighted sum of vp -> out[512]
__global__ void final_kernel(const float* __restrict__ aw, const float* __restrict__ vp,
                             float* __restrict__ out, int out_size)
{
    int c = threadIdx.x;  // 512
    float a[BB];
    float mx = -1e30f;
#pragma unroll
    for (int b = 0; b < BB; b++) { a[b] = aw[b]; mx = fmaxf(mx, a[b]); }
    float s = 0.f;
#pragma unroll
    for (int b = 0; b < BB; b++) { a[b] = expf(a[b] - mx); s += a[b]; }
    float inv = 1.f / s;
    float f = 0.f;
#pragma unroll
    for (int b = 0; b < BB; b++) f += a[b] * inv * vp[b * CC + c];
    if (c < out_size) out[c] = f;
}

// ---------------------------------------------------------------------------------------------
extern "C" void kernel_launch(void* const* d_in, const int* in_sizes, int n_in,
                              void* d_out, int out_size)
{
    const float* qry   = (const float*)d_in[0];
    const float* spt   = (const float*)d_in[1];
    const float* mask  = (const float*)d_in[2];
    const float* w_wq  = (const float*)d_in[3];
    const float* b_wq  = (const float*)d_in[4];
    const float* w_wk  = (const float*)d_in[5];
    const float* b_wk  = (const float*)d_in[6];
    const float* w_wv1 = (const float*)d_in[7];
    const float* b_wv1 = (const float*)d_in[8];
    const float* w_wv2 = (const float*)d_in[9];
    const float* b_wv2 = (const float*)d_in[10];
    const float* gamma1 = (const float*)d_in[11];
    const float* gamma2 = (const float*)d_in[12];
    const float* ca_wq = (const float*)d_in[13];
    const float* ca_bq = (const float*)d_in[14];
    const float* ca_wk = (const float*)d_in[15];
    const float* ca_bk = (const float*)d_in[16];
    const float* ca_wv = (const float*)d_in[17];
    const float* ca_bv = (const float*)d_in[18];
    const float* ca_wo = (const float*)d_in[19];
    const float* ca_bo = (const float*)d_in[20];
    const float* pf_wq = (const float*)d_in[21];
    const float* pf_bq = (const float*)d_in[22];
    const float* pf_wk = (const float*)d_in[23];
    const float* pf_bk = (const float*)d_in[24];
    const float* pf_wv = (const float*)d_in[25];
    const float* pf_bv = (const float*)d_in[26];

    float *p_q, *p_kt, *p_attn, *p_v1, *p_v2, *p_x1, *p_x2, *p_q2, *p_k2, *p_v2f;
    float *p_mid, *p_mid2, *p_pp, *p_pm, *p_proto, *p_qp, *p_kp, *p_vp, *p_aw;
    cudaGetSymbolAddress((void**)&p_q, g_q);
    cudaGetSymbolAddress((void**)&p_kt, g_kt);
    cudaGetSymbolAddress((void**)&p_attn, g_attn);
    cudaGetSymbolAddress((void**)&p_v1, g_v1);
    cudaGetSymbolAddress((void**)&p_v2, g_v2);
    cudaGetSymbolAddress((void**)&p_x1, g_x1);
    cudaGetSymbolAddress((void**)&p_x2, g_x2);
    cudaGetSymbolAddress((void**)&p_q2, g_q2);
    cudaGetSymbolAddress((void**)&p_k2, g_k2);
    cudaGetSymbolAddress((void**)&p_v2f, g_v2f);
    cudaGetSymbolAddress((void**)&p_mid, g_mid);
    cudaGetSymbolAddress((void**)&p_mid2, g_mid2);
    cudaGetSymbolAddress((void**)&p_pp, g_pp);
    cudaGetSymbolAddress((void**)&p_pm, g_pm);
    cudaGetSymbolAddress((void**)&p_proto, g_proto);
    cudaGetSymbolAddress((void**)&p_qp, g_qp);
    cudaGetSymbolAddress((void**)&p_kp, g_kp);
    cudaGetSymbolAddress((void**)&p_vp, g_vp);
    cudaGetSymbolAddress((void**)&p_aw, g_aw);

    const long CHW  = (long)CC * HWN;
    const long HWD  = (long)HWN * DD;
    const long HWHW = (long)HWN * HWN;
    dim3 blk(256);

    // 1) q[b,n,d] = qry^T @ w_wq^T + b_wq      (M=2304, N=64, K=512)
    hgemm_kernel<<<dim3(1, 18, BB), blk>>>(HWN, DD, CC,
        qry, 1, HWN, CHW,  w_wq, 1, CC, 0,
        p_q, DD, HWD,  b_wq, 1,  nullptr, 1.f,  nullptr, 0, 0);
    // 2) kt[b,m,d] = spt^T @ w_wk^T + b_wk
    hgemm_kernel<<<dim3(1, 18, BB), blk>>>(HWN, DD, CC,
        spt, 1, HWN, CHW,  w_wk, 1, CC, 0,
        p_kt, DD, HWD,  b_wk, 1,  nullptr, 1.f,  nullptr, 0, 0);
    // 3) attn[n,m] = q[n,:]·kt[m,:]            (M=N=2304, K=64)
    hgemm_kernel<<<dim3(18, 18, BB), blk>>>(HWN, HWN, DD,
        p_q, DD, 1, HWD,  p_kt, 1, DD, HWD,
        p_attn, HWN, HWHW,  nullptr, 0,  nullptr, 1.f,  nullptr, 0, 0);
    // 4) softmax rows
    softmax2304<<<BB * HWN, 256>>>(p_attn);
    // 5) v1 = w_wv1 @ qry + b_wv1 (per-row bias)   (M=512, N=2304, K=512)
    hgemm_kernel<<<dim3(18, 4, BB), blk>>>(CC, HWN, CC,
        w_wv1, CC, 1, 0,  qry, HWN, 1, CHW,
        p_v1, HWN, CHW,  b_wv1, 2,  nullptr, 1.f,  nullptr, 0, 0);
    // 6) v2 = w_wv2 @ spt + b_wv2
    hgemm_kernel<<<dim3(18, 4, BB), blk>>>(CC, HWN, CC,
        w_wv2, CC, 1, 0,  spt, HWN, 1, CHW,
        p_v2, HWN, CHW,  b_wv2, 2,  nullptr, 1.f,  nullptr, 0, 0);
    // 7) x1[c,m] = gamma1 * sum_n v1[c,n]*attn[m,n] + qry[c,m]   (M=512, N=2304, K=2304)
    hgemm_kernel<<<dim3(18, 4, BB), blk>>>(CC, HWN, HWN,
        p_v1, HWN, 1, CHW,  p_attn, 1, HWN, HWHW,
        p_x1, HWN, CHW,  nullptr, 0,  gamma1, 1.f,  qry, HWN, CHW);
    // 8) x2[c,m] = gamma2 * sum_n v2[c,n]*attn[n,m] + spt[c,m]
    hgemm_kernel<<<dim3(18, 4, BB), blk>>>(CC, HWN, HWN,
        p_v2, HWN, 1, CHW,  p_attn, HWN, 1, HWHW,
        p_x2, HWN, CHW,  nullptr, 0,  gamma2, 1.f,  spt, HWN, CHW);
    // 9) q2[n,j] = x1^T @ ca_wq^T + ca_bq      (M=2304, N=512, K=512)
    hgemm_kernel<<<dim3(4, 18, BB), blk>>>(HWN, CC, CC,
        p_x1, 1, HWN, CHW,  ca_wq, 1, CC, 0,
        p_q2, CC, CHW,  ca_bq, 1,  nullptr, 1.f,  nullptr, 0, 0);
    // 10) k2
    hgemm_kernel<<<dim3(4, 18, BB), blk>>>(HWN, CC, CC,
        p_x2, 1, HWN, CHW,  ca_wk, 1, CC, 0,
        p_k2, CC, CHW,  ca_bk, 1,  nullptr, 1.f,  nullptr, 0, 0);
    // 11) v2f
    hgemm_kernel<<<dim3(4, 18, BB), blk>>>(HWN, CC, CC,
        p_x2, 1, HWN, CHW,  ca_wv, 1, CC, 0,
        p_v2f, CC, CHW,  ca_bv, 1,  nullptr, 1.f,  nullptr, 0, 0);
    // 12) scores[n,m] = q2[n,:]·k2[m,:] / sqrt(512)   (M=N=2304, K=512) -> reuse g_attn
    hgemm_kernel<<<dim3(18, 18, BB), blk>>>(HWN, HWN, CC,
        p_q2, CC, 1, CHW,  p_k2, 1, CC, CHW,
        p_attn, HWN, HWHW,  nullptr, 0,  nullptr, 0.044194173824159216f,  nullptr, 0, 0);
    // 13) softmax rows
    softmax2304<<<BB * HWN, 256>>>(p_attn);
    // 14) mid[n,c] = sum_m attn2[n,m]*v2f[m,c]   (M=2304, N=512, K=2304)
    hgemm_kernel<<<dim3(4, 18, BB), blk>>>(HWN, CC, HWN,
        p_attn, HWN, 1, HWHW,  p_v2f, CC, 1, CHW,
        p_mid, CC, CHW,  nullptr, 0,  nullptr, 1.f,  nullptr, 0, 0);
    // 15) mid2 = mid @ ca_wo^T + ca_bo
    hgemm_kernel<<<dim3(4, 18, BB), blk>>>(HWN, CC, CC,
        p_mid, CC, 1, CHW,  ca_wo, 1, CC, 0,
        p_mid2, CC, CHW,  ca_bo, 1,  nullptr, 1.f,  nullptr, 0, 0);
    // 16) masked pooling -> proto
    proto_partial<<<dim3(18, BB), 512>>>(p_mid2, mask, p_pp, p_pm);
    proto_reduce<<<BB, 512>>>(p_pp, p_pm, p_proto);
    // 17) pf projections
    pf_gemv<<<dim3(CC / 8, 3, BB), 256>>>(p_proto,
        pf_wq, pf_bq, pf_wk, pf_bk, pf_wv, pf_bv, p_qp, p_kp, p_vp);
    // 18) aw[b] = qp[b]·kp[b]
    aw_kernel<<<BB, 256>>>(p_qp, p_kp, p_aw);
    // 19) softmax over batch + weighted sum -> out
    final_kernel<<<1, 512>>>(p_aw, p_vp, (float*)d_out, out_size);
}

// round 8
// speedup vs baseline: 7.2556x; 1.8683x over previous
#include <cuda_runtime.h>
#include <cuda_fp16.h>
#include <math.h>
#include <stdint.h>

#define BB 8
#define CC 512
#define DD 64
#define HWN 2304  // 48*48

// ---------------- scratch (static device globals; no allocation) ----------------
__device__ __half h_qryT[(size_t)BB*HWN*CC];   // [b][n][c]
__device__ __half h_sptT[(size_t)BB*HWN*CC];
__device__ __half h_wq [DD*CC];
__device__ __half h_wk [DD*CC];
__device__ __half h_wv1[CC*CC];
__device__ __half h_wv2[CC*CC];
__device__ __half h_cawq[CC*CC];
__device__ __half h_cawk[CC*CC];
__device__ __half h_cawv[CC*CC];
__device__ __half h_cawo[CC*CC];
__device__ __half h_q  [(size_t)BB*HWN*DD];
__device__ __half h_kt [(size_t)BB*HWN*DD];
__device__ float  g_scores[(size_t)BB*HWN*HWN];
__device__ __half h_S  [(size_t)BB*HWN*HWN];
__device__ __half h_ST [(size_t)BB*HWN*HWN];
__device__ __half h_v1 [(size_t)BB*CC*HWN];    // [b][c][n]
__device__ __half h_v2 [(size_t)BB*CC*HWN];
__device__ __half h_x1 [(size_t)BB*HWN*CC];    // [b][m][c]
__device__ __half h_x2 [(size_t)BB*HWN*CC];
__device__ __half h_q2 [(size_t)BB*HWN*CC];
__device__ __half h_k2 [(size_t)BB*HWN*CC];
__device__ __half h_v2fT[(size_t)BB*CC*HWN];   // [b][c][m]
__device__ __half h_mid[(size_t)BB*HWN*CC];
__device__ float  g_mid2[(size_t)BB*HWN*CC];
__device__ float  g_pp [(size_t)BB*18*CC];
__device__ float  g_pm [BB*18];
__device__ float  g_proto[BB*CC];
__device__ float  g_qp [BB*CC];
__device__ float  g_kp [BB*CC];
__device__ float  g_vp [BB*CC];
__device__ float  g_aw [BB];

// ======================= helpers =======================
__device__ __forceinline__ uint32_t smem_u32(const void* p) {
    uint32_t a;
    asm("{ .reg .u64 t; cvta.to.shared.u64 t, %1; cvt.u32.u64 %0, t; }" : "=r"(a) : "l"(p));
    return a;
}
__device__ __forceinline__ void cpa16(uint32_t dst, const void* src, int sz) {
    asm volatile("cp.async.ca.shared.global [%0], [%1], 16, %2;\n"
                 :: "r"(dst), "l"(src), "r"(sz));
}
#define CPA_COMMIT() asm volatile("cp.async.commit_group;\n" ::: "memory")
#define CPA_WAIT1()  asm volatile("cp.async.wait_group 1;\n" ::: "memory")
#define CPA_WAIT0()  asm volatile("cp.async.wait_group 0;\n" ::: "memory")

// ---------------- fp16 tensor-core GEMM, cp.async double-buffered ----------------
// C[i,j] = alpha*sum_k A[i][k]*B[j][k] (+bias)(+res). A,B fp16 row-major k-contig.
// Block tile 128x128, K-tile 32, 2 stages. 8 warps: 2(M) x 4(N), warp tile 64x32.
#define LDS_ROW 40   // 32 + 8 pad halves = 80B (16B-aligned), 20*r mod 32 distinct

template <bool OUT_HALF>
__global__ __launch_bounds__(256, 2)
void hgemm2(int M, int N, int K,
            const __half* __restrict__ A, int lda, long bsA,
            const __half* __restrict__ B, int ldb, long bsB,
            void* __restrict__ Cv, int ldc, long bsC,
            const float* __restrict__ bias, int bias_mode,   // 0 none, 1 per-col(j), 2 per-row(i)
            const float* __restrict__ alpha_ptr, float alpha_const,
            const __half* __restrict__ Rm, int ldr, long bsR)
{
    __shared__ __half As[2][128][LDS_ROW];
    __shared__ __half Bs[2][128][LDS_ROW];

    int bz = blockIdx.z;
    A += (long)bz * bsA;
    B += (long)bz * bsB;
    if (Rm) Rm += (long)bz * bsR;

    int i0 = blockIdx.y * 128, j0 = blockIdx.x * 128;
    int tid = threadIdx.x;
    int lane = tid & 31, wid = tid >> 5;
    int warp_m = (wid & 1) * 64;
    int warp_n = (wid >> 1) * 32;
    int g = lane >> 2;        // 0..7
    int tg = lane & 3;        // 0..3

    uint32_t sA = smem_u32(&As[0][0][0]);
    uint32_t sB = smem_u32(&Bs[0][0][0]);
    const uint32_t stageBytes = 128 * LDS_ROW * 2;

    // per-thread copy tasks: 512 chunks per operand per stage, 2 per thread
    int crow = tid >> 2;          // 0..63 -> two rows: crow, crow+64
    int cch  = tid & 3;           // chunk 0..3 (16B each)

    auto load_tile = [&](int st, int kt) {
        int k0 = kt * 32;
#pragma unroll
        for (int h = 0; h < 2; h++) {
            int row = crow + h * 64;
            uint32_t off = (uint32_t)(row * LDS_ROW + cch * 8) * 2;
            cpa16(sA + st * stageBytes + off,
                  A + (long)(i0 + row) * lda + k0 + cch * 8, 16);
            int gj = j0 + row;
            cpa16(sB + st * stageBytes + off,
                  B + (long)gj * ldb + k0 + cch * 8, (gj < N) ? 16 : 0);
        }
    };

    float acc[4][4][4];
#pragma unroll
    for (int a = 0; a < 4; a++)
#pragma unroll
        for (int b = 0; b < 4; b++)
#pragma unroll
            for (int c = 0; c < 4; c++) acc[a][b][c] = 0.f;

    int T = K / 32;
    load_tile(0, 0);
    CPA_COMMIT();

    for (int kt = 0; kt < T; kt++) {
        int st = kt & 1;
        if (kt + 1 < T) {
            load_tile(st ^ 1, kt + 1);
            CPA_COMMIT();
            CPA_WAIT1();
        } else {
            CPA_WAIT0();
        }
        __syncthreads();

#pragma unroll
        for (int ks = 0; ks < 2; ks++) {
            int kb = ks * 16;
            uint32_t a[4][4];
#pragma unroll
            for (int mt = 0; mt < 4; mt++) {
                int r = warp_m + mt * 16 + g;
                a[mt][0] = *(const uint32_t*)&As[st][r][kb + 2 * tg];
                a[mt][1] = *(const uint32_t*)&As[st][r + 8][kb + 2 * tg];
                a[mt][2] = *(const uint32_t*)&As[st][r][kb + 2 * tg + 8];
                a[mt][3] = *(const uint32_t*)&As[st][r + 8][kb + 2 * tg + 8];
            }
            uint32_t b[4][2];
#pragma unroll
            for (int nt = 0; nt < 4; nt++) {
                int cidx = warp_n + nt * 8 + g;
                b[nt][0] = *(const uint32_t*)&Bs[st][cidx][kb + 2 * tg];
                b[nt][1] = *(const uint32_t*)&Bs[st][cidx][kb + 2 * tg + 8];
            }
#pragma unroll
            for (int mt = 0; mt < 4; mt++)
#pragma unroll
                for (int nt = 0; nt < 4; nt++) {
                    asm volatile(
                        "mma.sync.aligned.m16n8k16.row.col.f32.f16.f16.f32 "
                        "{%0,%1,%2,%3}, {%4,%5,%6,%7}, {%8,%9}, {%0,%1,%2,%3};\n"
                        : "+f"(acc[mt][nt][0]), "+f"(acc[mt][nt][1]),
                          "+f"(acc[mt][nt][2]), "+f"(acc[mt][nt][3])
                        : "r"(a[mt][0]), "r"(a[mt][1]), "r"(a[mt][2]), "r"(a[mt][3]),
                          "r"(b[nt][0]), "r"(b[nt][1]));
                }
        }
        __syncthreads();
    }

    float alpha = alpha_const;
    if (alpha_ptr) alpha *= *alpha_ptr;

    float*  Cf = (float*)Cv;
    __half* Ch = (__half*)Cv;
    if (OUT_HALF) Ch += (long)bz * bsC; else Cf += (long)bz * bsC;

#pragma unroll
    for (int mt = 0; mt < 4; mt++) {
#pragma unroll
        for (int nt = 0; nt < 4; nt++) {
            int gj = j0 + warp_n + nt * 8 + tg * 2;
            if (gj >= N) continue;
#pragma unroll
            for (int half_row = 0; half_row < 2; half_row++) {
                int gi = i0 + warp_m + mt * 16 + g + half_row * 8;
                float v0 = alpha * acc[mt][nt][half_row * 2];
                float v1 = alpha * acc[mt][nt][half_row * 2 + 1];
                if (bias_mode == 1) { v0 += bias[gj]; v1 += bias[gj + 1]; }
                else if (bias_mode == 2) { float bb = bias[gi]; v0 += bb; v1 += bb; }
                if (Rm) {
                    uint32_t rr = *(const uint32_t*)(Rm + (long)gi * ldr + gj);
                    __half2 rh = *(__half2*)&rr;
                    v0 += __half2float(rh.x);
                    v1 += __half2float(rh.y);
                }
                if (OUT_HALF) {
                    __half2 o = __floats2half2_rn(v0, v1);
                    *(uint32_t*)(Ch + (long)gi * ldc + gj) = *(uint32_t*)&o;
                } else {
                    *(float2*)(Cf + (long)gi * ldc + gj) = make_float2(v0, v1);
                }
            }
        }
    }
}

// ---------------- fp32 -> fp16 copy (weights) ----------------
__global__ void f2h_copy(const float* __restrict__ s, __half* __restrict__ d, int n)
{
    int i = blockIdx.x * 1024 + threadIdx.x * 4;
    if (i + 3 < n) {
        float4 f = *(const float4*)(s + i);
        __half2 a = __floats2half2_rn(f.x, f.y);
        __half2 b = __floats2half2_rn(f.z, f.w);
        *(uint2*)(d + i) = make_uint2(*(uint32_t*)&a, *(uint32_t*)&b);
    }
}

// ---------------- transpose+convert: fp32 [C][HWN] -> fp16 [HWN][C], per batch ----
__global__ void tcvt_kernel(const float* __restrict__ src, __half* __restrict__ dst)
{
    __shared__ float tile[32][33];
    int b = blockIdx.z;
    int n0 = blockIdx.x * 32, c0 = blockIdx.y * 32;
    int tx = threadIdx.x, ty = threadIdx.y;  // (32, 8)
    const float* s = src + (long)b * CC * HWN;
    __half* d = dst + (long)b * HWN * CC;
#pragma unroll
    for (int i = 0; i < 4; i++)
        tile[ty + 8 * i][tx] = s[(long)(c0 + ty + 8 * i) * HWN + n0 + tx];
    __syncthreads();
#pragma unroll
    for (int i = 0; i < 4; i++)
        d[(long)(n0 + ty + 8 * i) * CC + c0 + tx] = __float2half(tile[tx][ty + 8 * i]);
}

// ---------------- fp16 transpose [HWN][HWN] per batch ----------------
__global__ void th_kernel(const __half* __restrict__ src, __half* __restrict__ dst)
{
    __shared__ __half tile[32][33];
    int b = blockIdx.z;
    int u0 = blockIdx.y * 32, v0 = blockIdx.x * 32;
    int tx = threadIdx.x, ty = threadIdx.y;  // (32, 8)
    const __half* s = src + (long)b * HWN * HWN;
    __half* d = dst + (long)b * HWN * HWN;
#pragma unroll
    for (int i = 0; i < 4; i++)
        tile[ty + 8 * i][tx] = s[(long)(u0 + ty + 8 * i) * HWN + v0 + tx];
    __syncthreads();
#pragma unroll
    for (int i = 0; i < 4; i++)
        d[(long)(v0 + ty + 8 * i) * HWN + u0 + tx] = tile[tx][ty + 8 * i];
}

// ---------------- row softmax over 2304 cols: fp32 in -> fp16 out ----------------
__global__ void softmax_h(const float* __restrict__ in, __half* __restrict__ out)
{
    long row = blockIdx.x;
    const float* p = in + row * (long)HWN;
    __half* o = out + row * (long)HWN;
    int t = threadIdx.x;
    float v[9];
    float mx = -1e30f;
#pragma unroll
    for (int i = 0; i < 9; i++) { v[i] = p[t + 256 * i]; mx = fmaxf(mx, v[i]); }

    __shared__ float red[256];
    red[t] = mx; __syncthreads();
    for (int s = 128; s > 0; s >>= 1) { if (t < s) red[t] = fmaxf(red[t], red[t + s]); __syncthreads(); }
    mx = red[0]; __syncthreads();

    float sm = 0.f;
#pragma unroll
    for (int i = 0; i < 9; i++) { v[i] = expf(v[i] - mx); sm += v[i]; }
    red[t] = sm; __syncthreads();
    for (int s = 128; s > 0; s >>= 1) { if (t < s) red[t] += red[t + s]; __syncthreads(); }
    float inv = 1.f / red[0];
#pragma unroll
    for (int i = 0; i < 9; i++) o[t + 256 * i] = __float2half(v[i] * inv);
}

// ---------------- masked pooling ----------------
__global__ void proto_partial(const float* __restrict__ mid2, const float* __restrict__ mask,
                              float* __restrict__ pp, float* __restrict__ pm)
{
    int b = blockIdx.y, chunk = blockIdx.x;
    int c = threadIdx.x;
    const float* mp = mask + (long)b * HWN + chunk * 128;
    const float* xp = mid2 + (long)b * HWN * CC + (long)chunk * 128 * CC + c;
    float acc = 0.f, ms = 0.f;
    for (int n = 0; n < 128; n++) {
        float m = mp[n];
        ms += m;
        acc += xp[(long)n * CC] * m;
    }
    pp[((long)b * 18 + chunk) * CC + c] = acc;
    if (c == 0) pm[b * 18 + chunk] = ms;
}

__global__ void proto_reduce(const float* __restrict__ pp, const float* __restrict__ pm,
                             float* __restrict__ proto)
{
    int b = blockIdx.x, c = threadIdx.x;
    float acc = 0.f, ms = 0.f;
    for (int k = 0; k < 18; k++) {
        acc += pp[((long)b * 18 + k) * CC + c];
        ms  += pm[b * 18 + k];
    }
    proto[b * CC + c] = acc / (ms + 1e-5f);
}

// ---------------- pf projections ----------------
__global__ void pf_gemv(const float* __restrict__ proto,
                        const float* __restrict__ wq, const float* __restrict__ bq,
                        const float* __restrict__ wk, const float* __restrict__ bk,
                        const float* __restrict__ wv, const float* __restrict__ bv,
                        float* __restrict__ qp, float* __restrict__ kp, float* __restrict__ vp)
{
    int b = blockIdx.z, which = blockIdx.y;
    const float* W    = (which == 0) ? wq : (which == 1) ? wk : wv;
    const float* bias = (which == 0) ? bq : (which == 1) ? bk : bv;
    float* out        = (which == 0) ? qp : (which == 1) ? kp : vp;
    int warp = threadIdx.x >> 5, lane = threadIdx.x & 31;
    int c2 = blockIdx.x * 8 + warp;
    const float* pr = proto + b * CC;
    const float* wr = W + (long)c2 * CC;
    float acc = 0.f;
    for (int c = lane; c < CC; c += 32) acc += pr[c] * wr[c];
#pragma unroll
    for (int o = 16; o > 0; o >>= 1) acc += __shfl_xor_sync(0xFFFFFFFFu, acc, o);
    if (lane == 0) out[b * CC + c2] = acc + bias[c2];
}

__global__ void aw_kernel(const float* __restrict__ qp, const float* __restrict__ kp,
                          float* __restrict__ aw)
{
    int b = blockIdx.x, t = threadIdx.x;
    float acc = 0.f;
    for (int c = t; c < CC; c += 256) acc += qp[b * CC + c] * kp[b * CC + c];
    __shared__ float red[256];
    red[t] = acc; __syncthreads();
    for (int s = 128; s > 0; s >>= 1) { if (t < s) red[t] += red[t + s]; __syncthreads(); }
    if (t == 0) aw[b] = red[0];
}

__global__ void final_kernel(const float* __restrict__ aw, const float* __restrict__ vp,
                             float* __restrict__ out, int out_size)
{
    int c = threadIdx.x;
    float a[BB];
    float mx = -1e30f;
#pragma unroll
    for (int b = 0; b < BB; b++) { a[b] = aw[b]; mx = fmaxf(mx, a[b]); }
    float s = 0.f;
#pragma unroll
    for (int b = 0; b < BB; b++) { a[b] = expf(a[b] - mx); s += a[b]; }
    float inv = 1.f / s;
    float f = 0.f;
#pragma unroll
    for (int b = 0; b < BB; b++) f += a[b] * inv * vp[b * CC + c];
    if (c < out_size) out[c] = f;
}

// ---------------------------------------------------------------------------------------------
extern "C" void kernel_launch(void* const* d_in, const int* in_sizes, int n_in,
                              void* d_out, int out_size)
{
    const float* qry   = (const float*)d_in[0];
    const float* spt   = (const float*)d_in[1];
    const float* mask  = (const float*)d_in[2];
    const float* w_wq  = (const float*)d_in[3];
    const float* b_wq  = (const float*)d_in[4];
    const float* w_wk  = (const float*)d_in[5];
    const float* b_wk  = (const float*)d_in[6];
    const float* w_wv1 = (const float*)d_in[7];
    const float* b_wv1 = (const float*)d_in[8];
    const float* w_wv2 = (const float*)d_in[9];
    const float* b_wv2 = (const float*)d_in[10];
    const float* gamma1 = (const float*)d_in[11];
    const float* gamma2 = (const float*)d_in[12];
    const float* ca_wq = (const float*)d_in[13];
    const float* ca_bq = (const float*)d_in[14];
    const float* ca_wk = (const float*)d_in[15];
    const float* ca_bk = (const float*)d_in[16];
    const float* ca_wv = (const float*)d_in[17];
    const float* ca_bv = (const float*)d_in[18];
    const float* ca_wo = (const float*)d_in[19];
    const float* ca_bo = (const float*)d_in[20];
    const float* pf_wq = (const float*)d_in[21];
    const float* pf_bq = (const float*)d_in[22];
    const float* pf_wk = (const float*)d_in[23];
    const float* pf_bk = (const float*)d_in[24];
    const float* pf_wv = (const float*)d_in[25];
    const float* pf_bv = (const float*)d_in[26];

    __half *pqT, *psT, *pwq, *pwk, *pwv1, *pwv2, *pcq, *pck, *pcv, *pco;
    __half *pq, *pkt, *pS, *pST, *pv1, *pv2, *px1, *px2, *pq2, *pk2, *pv2fT, *pmid;
    float *pscores, *pmid2, *ppp, *ppm, *pproto, *pqp, *pkp, *pvp, *paw;
    cudaGetSymbolAddress((void**)&pqT, h_qryT);
    cudaGetSymbolAddress((void**)&psT, h_sptT);
    cudaGetSymbolAddress((void**)&pwq, h_wq);
    cudaGetSymbolAddress((void**)&pwk, h_wk);
    cudaGetSymbolAddress((void**)&pwv1, h_wv1);
    cudaGetSymbolAddress((void**)&pwv2, h_wv2);
    cudaGetSymbolAddress((void**)&pcq, h_cawq);
    cudaGetSymbolAddress((void**)&pck, h_cawk);
    cudaGetSymbolAddress((void**)&pcv, h_cawv);
    cudaGetSymbolAddress((void**)&pco, h_cawo);
    cudaGetSymbolAddress((void**)&pq, h_q);
    cudaGetSymbolAddress((void**)&pkt, h_kt);
    cudaGetSymbolAddress((void**)&pscores, g_scores);
    cudaGetSymbolAddress((void**)&pS, h_S);
    cudaGetSymbolAddress((void**)&pST, h_ST);
    cudaGetSymbolAddress((void**)&pv1, h_v1);
    cudaGetSymbolAddress((void**)&pv2, h_v2);
    cudaGetSymbolAddress((void**)&px1, h_x1);
    cudaGetSymbolAddress((void**)&px2, h_x2);
    cudaGetSymbolAddress((void**)&pq2, h_q2);
    cudaGetSymbolAddress((void**)&pk2, h_k2);
    cudaGetSymbolAddress((void**)&pv2fT, h_v2fT);
    cudaGetSymbolAddress((void**)&pmid, h_mid);
    cudaGetSymbolAddress((void**)&pmid2, g_mid2);
    cudaGetSymbolAddress((void**)&ppp, g_pp);
    cudaGetSymbolAddress((void**)&ppm, g_pm);
    cudaGetSymbolAddress((void**)&pproto, g_proto);
    cudaGetSymbolAddress((void**)&pqp, g_qp);
    cudaGetSymbolAddress((void**)&pkp, g_kp);
    cudaGetSymbolAddress((void**)&pvp, g_vp);
    cudaGetSymbolAddress((void**)&paw, g_aw);

    const long NC   = (long)HWN * CC;     // 2304*512
    const long ND   = (long)HWN * DD;
    const long NN   = (long)HWN * HWN;
    dim3 blk(256);
    const float inv_sqrt_c = 0.044194173824159216f;

    // 0a) weights -> fp16
    f2h_copy<<<(DD * CC + 1023) / 1024, 256>>>(w_wq, pwq, DD * CC);
    f2h_copy<<<(DD * CC + 1023) / 1024, 256>>>(w_wk, pwk, DD * CC);
    f2h_copy<<<(CC * CC + 1023) / 1024, 256>>>(w_wv1, pwv1, CC * CC);
    f2h_copy<<<(CC * CC + 1023) / 1024, 256>>>(w_wv2, pwv2, CC * CC);
    f2h_copy<<<(CC * CC + 1023) / 1024, 256>>>(ca_wq, pcq, CC * CC);
    f2h_copy<<<(CC * CC + 1023) / 1024, 256>>>(ca_wk, pck, CC * CC);
    f2h_copy<<<(CC * CC + 1023) / 1024, 256>>>(ca_wv, pcv, CC * CC);
    f2h_copy<<<(CC * CC + 1023) / 1024, 256>>>(ca_wo, pco, CC * CC);
    // 0b) qry/spt -> fp16 transposed [n][c]
    tcvt_kernel<<<dim3(HWN / 32, CC / 32, BB), dim3(32, 8)>>>(qry, pqT);
    tcvt_kernel<<<dim3(HWN / 32, CC / 32, BB), dim3(32, 8)>>>(spt, psT);

    // 1) q[n][d] = qryT·wq^T + b    (M=2304,N=64,K=512)
    hgemm2<true><<<dim3(1, 18, BB), blk>>>(HWN, DD, CC,
        pqT, CC, NC,  pwq, CC, 0,  pq, DD, ND,  b_wq, 1, nullptr, 1.f, nullptr, 0, 0);
    // 2) kt
    hgemm2<true><<<dim3(1, 18, BB), blk>>>(HWN, DD, CC,
        psT, CC, NC,  pwk, CC, 0,  pkt, DD, ND,  b_wk, 1, nullptr, 1.f, nullptr, 0, 0);
    // 3) scores1[n][m] = q·kt^T   (M=N=2304,K=64)
    hgemm2<false><<<dim3(18, 18, BB), blk>>>(HWN, HWN, DD,
        pq, DD, ND,  pkt, DD, ND,  pscores, HWN, NN,  nullptr, 0, nullptr, 1.f, nullptr, 0, 0);
    // 4) softmax -> S fp16 ; transpose -> ST
    softmax_h<<<BB * HWN, 256>>>(pscores, pS);
    th_kernel<<<dim3(HWN / 32, HWN / 32, BB), dim3(32, 8)>>>(pS, pST);
    // 5) v1[c][n] = wv1·qry + b  (M=512,N=2304,K=512), bias per-row c
    hgemm2<true><<<dim3(18, 4, BB), blk>>>(CC, HWN, CC,
        pwv1, CC, 0,  pqT, CC, NC,  pv1, HWN, (long)CC * HWN,  b_wv1, 2, nullptr, 1.f, nullptr, 0, 0);
    // 6) v2
    hgemm2<true><<<dim3(18, 4, BB), blk>>>(CC, HWN, CC,
        pwv2, CC, 0,  psT, CC, NC,  pv2, HWN, (long)CC * HWN,  b_wv2, 2, nullptr, 1.f, nullptr, 0, 0);
    // 7) x1[m][c] = gamma1·sum_n S[m][n]·v1[c][n] + qryT[m][c]  (M=2304,N=512,K=2304)
    hgemm2<true><<<dim3(4, 18, BB), blk>>>(HWN, CC, HWN,
        pS, HWN, NN,  pv1, HWN, (long)CC * HWN,  px1, CC, NC,
        nullptr, 0, gamma1, 1.f, pqT, CC, NC);
    // 8) x2[m][c] = gamma2·sum_n ST[m][n]·v2[c][n] + sptT[m][c]
    hgemm2<true><<<dim3(4, 18, BB), blk>>>(HWN, CC, HWN,
        pST, HWN, NN,  pv2, HWN, (long)CC * HWN,  px2, CC, NC,
        nullptr, 0, gamma2, 1.f, psT, CC, NC);
    // 9) q2[n][c2] = x1·ca_wq^T + b  (M=2304,N=512,K=512)
    hgemm2<true><<<dim3(4, 18, BB), blk>>>(HWN, CC, CC,
        px1, CC, NC,  pcq, CC, 0,  pq2, CC, NC,  ca_bq, 1, nullptr, 1.f, nullptr, 0, 0);
    // 10) k2
    hgemm2<true><<<dim3(4, 18, BB), blk>>>(HWN, CC, CC,
        px2, CC, NC,  pck, CC, 0,  pk2, CC, NC,  ca_bk, 1, nullptr, 1.f, nullptr, 0, 0);
    // 11) v2fT[c][m] = ca_wv·x2^T + b  (M=512,N=2304,K=512), bias per-row c
    hgemm2<true><<<dim3(18, 4, BB), blk>>>(CC, HWN, CC,
        pcv, CC, 0,  px2, CC, NC,  pv2fT, HWN, (long)CC * HWN,  ca_bv, 2, nullptr, 1.f, nullptr, 0, 0);
    // 12) scores2[n][m] = q2·k2^T /sqrt(C)  (M=N=2304,K=512)
    hgemm2<false><<<dim3(18, 18, BB), blk>>>(HWN, HWN, CC,
        pq2, CC, NC,  pk2, CC, NC,  pscores, HWN, NN,  nullptr, 0, nullptr, inv_sqrt_c, nullptr, 0, 0);
    // 13) softmax -> S2 fp16 (reuse h_S)
    softmax_h<<<BB * HWN, 256>>>(pscores, pS);
    // 14) mid[n][c] = sum_m S2[n][m]·v2fT[c][m]  (M=2304,N=512,K=2304)
    hgemm2<true><<<dim3(4, 18, BB), blk>>>(HWN, CC, HWN,
        pS, HWN, NN,  pv2fT, HWN, (long)CC * HWN,  pmid, CC, NC,
        nullptr, 0, nullptr, 1.f, nullptr, 0, 0);
    // 15) mid2[n][c] = mid·ca_wo^T + b -> fp32  (M=2304,N=512,K=512)
    hgemm2<false><<<dim3(4, 18, BB), blk>>>(HWN, CC, CC,
        pmid, CC, NC,  pco, CC, 0,  pmid2, CC, NC,  ca_bo, 1, nullptr, 1.f, nullptr, 0, 0);
    // 16) masked pooling -> proto
    proto_partial<<<dim3(18, BB), 512>>>(pmid2, mask, ppp, ppm);
    proto_reduce<<<BB, 512>>>(ppp, ppm, pproto);
    // 17) pf projections
    pf_gemv<<<dim3(CC / 8, 3, BB), 256>>>(pproto,
        pf_wq, pf_bq, pf_wk, pf_bk, pf_wv, pf_bv, pqp, pkp, pvp);
    // 18) aw[b] = qp[b]·kp[b]
    aw_kernel<<<BB, 256>>>(pqp, pkp, paw);
    // 19) softmax over batch + weighted sum -> out
    final_kernel<<<1, 512>>>(paw, pvp, (float*)d_out, out_size);
}

// round 12
// speedup vs baseline: 8.1159x; 1.1186x over previous
#include <cuda_runtime.h>
#include <cuda_fp16.h>
#include <math.h>
#include <stdint.h>

#define BB 8
#define CC 512
#define DD 64
#define HWN 2304  // 48*48

// ---------------- scratch (static device globals; no allocation) ----------------
__device__ __half h_qryT[(size_t)BB*HWN*CC];   // [b][n][c]
__device__ __half h_sptT[(size_t)BB*HWN*CC];
__device__ __half h_wq [DD*CC];
__device__ __half h_wk [DD*CC];
__device__ __half h_wv1[CC*CC];
__device__ __half h_wv2[CC*CC];
__device__ __half h_cawq[CC*CC];
__device__ __half h_cawk[CC*CC];
__device__ __half h_cawv[CC*CC];
__device__ __half h_cawo[CC*CC];
__device__ __half h_q  [(size_t)BB*HWN*DD];
__device__ __half h_kt [(size_t)BB*HWN*DD];
__device__ float  g_scores[(size_t)BB*HWN*HWN];
__device__ __half h_S  [(size_t)BB*HWN*HWN];
__device__ __half h_ST [(size_t)BB*HWN*HWN];
__device__ __half h_v1 [(size_t)BB*CC*HWN];    // [b][c][n]
__device__ __half h_v2 [(size_t)BB*CC*HWN];
__device__ __half h_x1 [(size_t)BB*HWN*CC];    // [b][m][c]
__device__ __half h_x2 [(size_t)BB*HWN*CC];
__device__ __half h_q2 [(size_t)BB*HWN*CC];
__device__ __half h_k2 [(size_t)BB*HWN*CC];
__device__ __half h_v2fT[(size_t)BB*CC*HWN];   // [b][c][m]
__device__ __half h_mid[(size_t)BB*HWN*CC];
__device__ float  g_mid2[(size_t)BB*HWN*CC];
__device__ float  g_pp [(size_t)BB*18*CC];
__device__ float  g_pm [BB*18];
__device__ float  g_proto[BB*CC];
__device__ float  g_qp [BB*CC];
__device__ float  g_kp [BB*CC];
__device__ float  g_vp [BB*CC];
__device__ float  g_aw [BB];

// ======================= helpers =======================
__device__ __forceinline__ uint32_t smem_u32(const void* p) {
    uint32_t a;
    asm("{ .reg .u64 t; cvta.to.shared.u64 t, %1; cvt.u32.u64 %0, t; }" : "=r"(a) : "l"(p));
    return a;
}
__device__ __forceinline__ void cpa16(uint32_t dst, const void* src, int sz) {
    asm volatile("cp.async.ca.shared.global [%0], [%1], 16, %2;\n"
                 :: "r"(dst), "l"(src), "r"(sz));
}
#define CPA_COMMIT() asm volatile("cp.async.commit_group;\n" ::: "memory")
#define CPA_WAIT1()  asm volatile("cp.async.wait_group 1;\n" ::: "memory")
#define CPA_WAIT0()  asm volatile("cp.async.wait_group 0;\n" ::: "memory")

// ---------------- fp16 tensor-core GEMM, cp.async + ldmatrix --------------------
// C[i,j] = alpha*sum_k A[i][k]*B[j][k] (+bias)(+res). A,B fp16 row-major k-contig.
// Block tile 128x128, K-tile 32, 2 stages. 8 warps: 2(M) x 4(N), warp tile 64x32.
#define LDS_ROW 40   // 32 + 8 pad halves = 80B; ldmatrix rows hit disjoint bank quads

template <bool OUT_HALF>
__global__ __launch_bounds__(256, 2)
void hgemm2(int M, int N, int K,
            const __half* __restrict__ A, int lda, long bsA,
            const __half* __restrict__ B, int ldb, long bsB,
            void* __restrict__ Cv, int ldc, long bsC,
            const float* __restrict__ bias, int bias_mode,   // 0 none, 1 per-col(j), 2 per-row(i)
            const float* __restrict__ alpha_ptr, float alpha_const,
            const __half* __restrict__ Rm, int ldr, long bsR)
{
    __shared__ __half As[2][128][LDS_ROW];
    __shared__ __half Bs[2][128][LDS_ROW];

    int bz = blockIdx.z;
    A += (long)bz * bsA;
    B += (long)bz * bsB;
    if (Rm) Rm += (long)bz * bsR;

    int i0 = blockIdx.y * 128, j0 = blockIdx.x * 128;
    int tid = threadIdx.x;
    int lane = tid & 31, wid = tid >> 5;
    int warp_m = (wid & 1) * 64;
    int warp_n = (wid >> 1) * 32;
    int g = lane >> 2;        // 0..7
    int tg = lane & 3;        // 0..3

    uint32_t sA = smem_u32(&As[0][0][0]);
    uint32_t sB = smem_u32(&Bs[0][0][0]);
    const uint32_t stageBytes = 128 * LDS_ROW * 2;

    // ldmatrix per-lane source rows/cols (within the warp tile)
    int lm_arow = warp_m + (lane & 7) + 8 * ((lane >> 3) & 1);
    int lm_acol = 8 * ((lane >> 4) & 1);
    int lm_brow = warp_n + (lane & 7) + 8 * ((lane >> 4) & 1);
    int lm_bcol = 8 * ((lane >> 3) & 1);

    // per-thread copy tasks: 512 chunks per operand per stage, 2 per thread
    int crow = tid >> 2;          // 0..63 -> two rows: crow, crow+64
    int cch  = tid & 3;           // chunk 0..3 (16B each)

    auto load_tile = [&](int st, int kt) {
        int k0 = kt * 32;
#pragma unroll
        for (int h = 0; h < 2; h++) {
            int row = crow + h * 64;
            uint32_t off = (uint32_t)(row * LDS_ROW + cch * 8) * 2;
            cpa16(sA + st * stageBytes + off,
                  A + (long)(i0 + row) * lda + k0 + cch * 8, 16);
            int gj = j0 + row;
            cpa16(sB + st * stageBytes + off,
                  B + (long)gj * ldb + k0 + cch * 8, (gj < N) ? 16 : 0);
        }
    };

    float acc[4][4][4];
#pragma unroll
    for (int a = 0; a < 4; a++)
#pragma unroll
        for (int b = 0; b < 4; b++)
#pragma unroll
            for (int c = 0; c < 4; c++) acc[a][b][c] = 0.f;

    int T = K / 32;
    load_tile(0, 0);
    CPA_COMMIT();

    for (int kt = 0; kt < T; kt++) {
        int st = kt & 1;
        if (kt + 1 < T) {
            load_tile(st ^ 1, kt + 1);
            CPA_COMMIT();
            CPA_WAIT1();
        } else {
            CPA_WAIT0();
        }
        __syncthreads();

        uint32_t sAst = sA + st * stageBytes;
        uint32_t sBst = sB + st * stageBytes;
#pragma unroll
        for (int ks = 0; ks < 2; ks++) {
            int kb = ks * 16;
            uint32_t a[4][4];
#pragma unroll
            for (int mt = 0; mt < 4; mt++) {
                uint32_t addr = sAst +
                    (uint32_t)((lm_arow + mt * 16) * LDS_ROW + kb + lm_acol) * 2;
                asm volatile("ldmatrix.sync.aligned.m8n8.x4.shared.b16 {%0,%1,%2,%3}, [%4];"
                    : "=r"(a[mt][0]), "=r"(a[mt][1]), "=r"(a[mt][2]), "=r"(a[mt][3])
                    : "r"(addr));
            }
            uint32_t b[4][2];
#pragma unroll
            for (int np = 0; np < 2; np++) {
                uint32_t addr = sBst +
                    (uint32_t)((lm_brow + np * 16) * LDS_ROW + kb + lm_bcol) * 2;
                asm volatile("ldmatrix.sync.aligned.m8n8.x4.shared.b16 {%0,%1,%2,%3}, [%4];"
                    : "=r"(b[2 * np][0]), "=r"(b[2 * np][1]),
                      "=r"(b[2 * np + 1][0]), "=r"(b[2 * np + 1][1])
                    : "r"(addr));
            }
#pragma unroll
            for (int mt = 0; mt < 4; mt++)
#pragma unroll
                for (int nt = 0; nt < 4; nt++) {
                    asm volatile(
                        "mma.sync.aligned.m16n8k16.row.col.f32.f16.f16.f32 "
                        "{%0,%1,%2,%3}, {%4,%5,%6,%7}, {%8,%9}, {%0,%1,%2,%3};\n"
                        : "+f"(acc[mt][nt][0]), "+f"(acc[mt][nt][1]),
                          "+f"(acc[mt][nt][2]), "+f"(acc[mt][nt][3])
                        : "r"(a[mt][0]), "r"(a[mt][1]), "r"(a[mt][2]), "r"(a[mt][3]),
                          "r"(b[nt][0]), "r"(b[nt][1]));
                }
        }
        __syncthreads();
    }

    float alpha = alpha_const;
    if (alpha_ptr) alpha *= *alpha_ptr;

    float*  Cf = (float*)Cv;
    __half* Ch = (__half*)Cv;
    if (OUT_HALF) Ch += (long)bz * bsC; else Cf += (long)bz * bsC;

#pragma unroll
    for (int mt = 0; mt < 4; mt++) {
#pragma unroll
        for (int nt = 0; nt < 4; nt++) {
            int gj = j0 + warp_n + nt * 8 + tg * 2;
            if (gj >= N) continue;
#pragma unroll
            for (int half_row = 0; half_row < 2; half_row++) {
                int gi = i0 + warp_m + mt * 16 + g + half_row * 8;
                float v0 = alpha * acc[mt][nt][half_row * 2];
                float v1 = alpha * acc[mt][nt][half_row * 2 + 1];
                if (bias_mode == 1) { v0 += bias[gj]; v1 += bias[gj + 1]; }
                else if (bias_mode == 2) { float bb = bias[gi]; v0 += bb; v1 += bb; }
                if (Rm) {
                    uint32_t rr = *(const uint32_t*)(Rm + (long)gi * ldr + gj);
                    __half2 rh = *(__half2*)&rr;
                    v0 += __half2float(rh.x);
                    v1 += __half2float(rh.y);
                }
                if (OUT_HALF) {
                    __half2 o = __floats2half2_rn(v0, v1);
                    *(uint32_t*)(Ch + (long)gi * ldc + gj) = *(uint32_t*)&o;
                } else {
                    *(float2*)(Cf + (long)gi * ldc + gj) = make_float2(v0, v1);
                }
            }
        }
    }
}

// ---------------- all weights fp32 -> fp16 in one launch ----------------
__global__ void w2h_all(const float* s0, const float* s1, const float* s2, const float* s3,
                        const float* s4, const float* s5, const float* s6, const float* s7,
                        __half* d0, __half* d1, __half* d2, __half* d3,
                        __half* d4, __half* d5, __half* d6, __half* d7)
{
    int which = blockIdx.y;
    const float* s; __half* d; int n;
    switch (which) {
        case 0: s = s0; d = d0; n = DD * CC; break;
        case 1: s = s1; d = d1; n = DD * CC; break;
        case 2: s = s2; d = d2; n = CC * CC; break;
        case 3: s = s3; d = d3; n = CC * CC; break;
        case 4: s = s4; d = d4; n = CC * CC; break;
        case 5: s = s5; d = d5; n = CC * CC; break;
        case 6: s = s6; d = d6; n = CC * CC; break;
        default: s = s7; d = d7; n = CC * CC; break;
    }
    int i = blockIdx.x * 1024 + threadIdx.x * 4;
    if (i + 3 < n) {
        float4 f = *(const float4*)(s + i);
        __half2 a = __floats2half2_rn(f.x, f.y);
        __half2 b = __floats2half2_rn(f.z, f.w);
        *(uint2*)(d + i) = make_uint2(*(uint32_t*)&a, *(uint32_t*)&b);
    }
}

// ---------------- transpose+convert: fp32 [C][HWN] -> fp16 [HWN][C], per batch ----
__global__ void tcvt_kernel(const float* __restrict__ src, __half* __restrict__ dst)
{
    __shared__ float tile[32][33];
    int b = blockIdx.z;
    int n0 = blockIdx.x * 32, c0 = blockIdx.y * 32;
    int tx = threadIdx.x, ty = threadIdx.y;  // (32, 8)
    const float* s = src + (long)b * CC * HWN;
    __half* d = dst + (long)b * HWN * CC;
#pragma unroll
    for (int i = 0; i < 4; i++)
        tile[ty + 8 * i][tx] = s[(long)(c0 + ty + 8 * i) * HWN + n0 + tx];
    __syncthreads();
#pragma unroll
    for (int i = 0; i < 4; i++)
        d[(long)(n0 + ty + 8 * i) * CC + c0 + tx] = __float2half(tile[tx][ty + 8 * i]);
}

// ---------------- fp16 transpose [HWN][HWN] per batch ----------------
__global__ void th_kernel(const __half* __restrict__ src, __half* __restrict__ dst)
{
    __shared__ __half tile[32][33];
    int b = blockIdx.z;
    int u0 = blockIdx.y * 32, v0 = blockIdx.x * 32;
    int tx = threadIdx.x, ty = threadIdx.y;  // (32, 8)
    const __half* s = src + (long)b * HWN * HWN;
    __half* d = dst + (long)b * HWN * HWN;
#pragma unroll
    for (int i = 0; i < 4; i++)
        tile[ty + 8 * i][tx] = s[(long)(u0 + ty + 8 * i) * HWN + v0 + tx];
    __syncthreads();
#pragma unroll
    for (int i = 0; i < 4; i++)
        d[(long)(v0 + ty + 8 * i) * HWN + u0 + tx] = tile[tx][ty + 8 * i];
}

// ---------------- row softmax over 2304 cols: fp32 in -> fp16 out ----------------
__global__ void softmax_h(const float* __restrict__ in, __half* __restrict__ out)
{
    long row = blockIdx.x;
    const float* p = in + row * (long)HWN;
    __half* o = out + row * (long)HWN;
    int t = threadIdx.x;
    float v[9];
    float mx = -1e30f;
#pragma unroll
    for (int i = 0; i < 9; i++) { v[i] = p[t + 256 * i]; mx = fmaxf(mx, v[i]); }

    __shared__ float red[256];
    red[t] = mx; __syncthreads();
    for (int s = 128; s > 0; s >>= 1) { if (t < s) red[t] = fmaxf(red[t], red[t + s]); __syncthreads(); }
    mx = red[0]; __syncthreads();

    float sm = 0.f;
#pragma unroll
    for (int i = 0; i < 9; i++) { v[i] = expf(v[i] - mx); sm += v[i]; }
    red[t] = sm; __syncthreads();
    for (int s = 128; s > 0; s >>= 1) { if (t < s) red[t] += red[t + s]; __syncthreads(); }
    float inv = 1.f / red[0];
#pragma unroll
    for (int i = 0; i < 9; i++) o[t + 256 * i] = __float2half(v[i] * inv);
}

// ---------------- masked pooling ----------------
__global__ void proto_partial(const float* __restrict__ mid2, const float* __restrict__ mask,
                              float* __restrict__ pp, float* __restrict__ pm)
{
    int b = blockIdx.y, chunk = blockIdx.x;
    int c = threadIdx.x;
    const float* mp = mask + (long)b * HWN + chunk * 128;
    const float* xp = mid2 + (long)b * HWN * CC + (long)chunk * 128 * CC + c;
    float acc = 0.f, ms = 0.f;
    for (int n = 0; n < 128; n++) {
        float m = mp[n];
        ms += m;
        acc += xp[(long)n * CC] * m;
    }
    pp[((long)b * 18 + chunk) * CC + c] = acc;
    if (c == 0) pm[b * 18 + chunk] = ms;
}

__global__ void proto_reduce(const float* __restrict__ pp, const float* __restrict__ pm,
                             float* __restrict__ proto)
{
    int b = blockIdx.x, c = threadIdx.x;
    float acc = 0.f, ms = 0.f;
    for (int k = 0; k < 18; k++) {
        acc += pp[((long)b * 18 + k) * CC + c];
        ms  += pm[b * 18 + k];
    }
    proto[b * CC + c] = acc / (ms + 1e-5f);
}

// ---------------- pf projections ----------------
__global__ void pf_gemv(const float* __restrict__ proto,
                        const float* __restrict__ wq, const float* __restrict__ bq,
                        const float* __restrict__ wk, const float* __restrict__ bk,
                        const float* __restrict__ wv, const float* __restrict__ bv,
                        float* __restrict__ qp, float* __restrict__ kp, float* __restrict__ vp)
{
    int b = blockIdx.z, which = blockIdx.y;
    const float* W    = (which == 0) ? wq : (which == 1) ? wk : wv;
    const float* bias = (which == 0) ? bq : (which == 1) ? bk : bv;
    float* out        = (which == 0) ? qp : (which == 1) ? kp : vp;
    int warp = threadIdx.x >> 5, lane = threadIdx.x & 31;
    int c2 = blockIdx.x * 8 + warp;
    const float* pr = proto + b * CC;
    const float* wr = W + (long)c2 * CC;
    float acc = 0.f;
    for (int c = lane; c < CC; c += 32) acc += pr[c] * wr[c];
#pragma unroll
    for (int o = 16; o > 0; o >>= 1) acc += __shfl_xor_sync(0xFFFFFFFFu, acc, o);
    if (lane == 0) out[b * CC + c2] = acc + bias[c2];
}

__global__ void aw_kernel(const float* __restrict__ qp, const float* __restrict__ kp,
                          float* __restrict__ aw)
{
    int b = blockIdx.x, t = threadIdx.x;
    float acc = 0.f;
    for (int c = t; c < CC; c += 256) acc += qp[b * CC + c] * kp[b * CC + c];
    __shared__ float red[256];
    red[t] = acc; __syncthreads();
    for (int s = 128; s > 0; s >>= 1) { if (t < s) red[t] += red[t + s]; __syncthreads(); }
    if (t == 0) aw[b] = red[0];
}

__global__ void final_kernel(const float* __restrict__ aw, const float* __restrict__ vp,
                             float* __restrict__ out, int out_size)
{
    int c = threadIdx.x;
    float a[BB];
    float mx = -1e30f;
#pragma unroll
    for (int b = 0; b < BB; b++) { a[b] = aw[b]; mx = fmaxf(mx, a[b]); }
    float s = 0.f;
#pragma unroll
    for (int b = 0; b < BB; b++) { a[b] = expf(a[b] - mx); s += a[b]; }
    float inv = 1.f / s;
    float f = 0.f;
#pragma unroll
    for (int b = 0; b < BB; b++) f += a[b] * inv * vp[b * CC + c];
    if (c < out_size) out[c] = f;
}

// ---------------------------------------------------------------------------------------------
extern "C" void kernel_launch(void* const* d_in, const int* in_sizes, int n_in,
                              void* d_out, int out_size)
{
    const float* qry   = (const float*)d_in[0];
    const float* spt   = (const float*)d_in[1];
    const float* mask  = (const float*)d_in[2];
    const float* w_wq  = (const float*)d_in[3];
    const float* b_wq  = (const float*)d_in[4];
    const float* w_wk  = (const float*)d_in[5];
    const float* b_wk  = (const float*)d_in[6];
    const float* w_wv1 = (const float*)d_in[7];
    const float* b_wv1 = (const float*)d_in[8];
    const float* w_wv2 = (const float*)d_in[9];
    const float* b_wv2 = (const float*)d_in[10];
    const float* gamma1 = (const float*)d_in[11];
    const float* gamma2 = (const float*)d_in[12];
    const float* ca_wq = (const float*)d_in[13];
    const float* ca_bq = (const float*)d_in[14];
    const float* ca_wk = (const float*)d_in[15];
    const float* ca_bk = (const float*)d_in[16];
    const float* ca_wv = (const float*)d_in[17];
    const float* ca_bv = (const float*)d_in[18];
    const float* ca_wo = (const float*)d_in[19];
    const float* ca_bo = (const float*)d_in[20];
    const float* pf_wq = (const float*)d_in[21];
    const float* pf_bq = (const float*)d_in[22];
    const float* pf_wk = (const float*)d_in[23];
    const float* pf_bk = (const float*)d_in[24];
    const float* pf_wv = (const float*)d_in[25];
    const float* pf_bv = (const float*)d_in[26];

    __half *pqT, *psT, *pwq, *pwk, *pwv1, *pwv2, *pcq, *pck, *pcv, *pco;
    __half *pq, *pkt, *pS, *pST, *pv1, *pv2, *px1, *px2, *pq2, *pk2, *pv2fT, *pmid;
    float *pscores, *pmid2, *ppp, *ppm, *pproto, *pqp, *pkp, *pvp, *paw;
    cudaGetSymbolAddress((void**)&pqT, h_qryT);
    cudaGetSymbolAddress((void**)&psT, h_sptT);
    cudaGetSymbolAddress((void**)&pwq, h_wq);
    cudaGetSymbolAddress((void**)&pwk, h_wk);
    cudaGetSymbolAddress((void**)&pwv1, h_wv1);
    cudaGetSymbolAddress((void**)&pwv2, h_wv2);
    cudaGetSymbolAddress((void**)&pcq, h_cawq);
    cudaGetSymbolAddress((void**)&pck, h_cawk);
    cudaGetSymbolAddress((void**)&pcv, h_cawv);
    cudaGetSymbolAddress((void**)&pco, h_cawo);
    cudaGetSymbolAddress((void**)&pq, h_q);
    cudaGetSymbolAddress((void**)&pkt, h_kt);
    cudaGetSymbolAddress((void**)&pscores, g_scores);
    cudaGetSymbolAddress((void**)&pS, h_S);
    cudaGetSymbolAddress((void**)&pST, h_ST);
    cudaGetSymbolAddress((void**)&pv1, h_v1);
    cudaGetSymbolAddress((void**)&pv2, h_v2);
    cudaGetSymbolAddress((void**)&px1, h_x1);
    cudaGetSymbolAddress((void**)&px2, h_x2);
    cudaGetSymbolAddress((void**)&pq2, h_q2);
    cudaGetSymbolAddress((void**)&pk2, h_k2);
    cudaGetSymbolAddress((void**)&pv2fT, h_v2fT);
    cudaGetSymbolAddress((void**)&pmid, h_mid);
    cudaGetSymbolAddress((void**)&pmid2, g_mid2);
    cudaGetSymbolAddress((void**)&ppp, g_pp);
    cudaGetSymbolAddress((void**)&ppm, g_pm);
    cudaGetSymbolAddress((void**)&pproto, g_proto);
    cudaGetSymbolAddress((void**)&pqp, g_qp);
    cudaGetSymbolAddress((void**)&pkp, g_kp);
    cudaGetSymbolAddress((void**)&pvp, g_vp);
    cudaGetSymbolAddress((void**)&paw, g_aw);

    const long NC   = (long)HWN * CC;     // 2304*512
    const long ND   = (long)HWN * DD;
    const long NN   = (long)HWN * HWN;
    dim3 blk(256);
    const float inv_sqrt_c = 0.044194173824159216f;

    // 0a) all weights -> fp16, one launch
    w2h_all<<<dim3((CC * CC) / 1024, 8), 256>>>(
        w_wq, w_wk, w_wv1, w_wv2, ca_wq, ca_wk, ca_wv, ca_wo,
        pwq, pwk, pwv1, pwv2, pcq, pck, pcv, pco);
    // 0b) qry/spt -> fp16 transposed [n][c]
    tcvt_kernel<<<dim3(HWN / 32, CC / 32, BB), dim3(32, 8)>>>(qry, pqT);
    tcvt_kernel<<<dim3(HWN / 32, CC / 32, BB), dim3(32, 8)>>>(spt, psT);

    // 1) q[n][d] = qryT·wq^T + b    (M=2304,N=64,K=512)
    hgemm2<true><<<dim3(1, 18, BB), blk>>>(HWN, DD, CC,
        pqT, CC, NC,  pwq, CC, 0,  pq, DD, ND,  b_wq, 1, nullptr, 1.f, nullptr, 0, 0);
    // 2) kt
    hgemm2<true><<<dim3(1, 18, BB), blk>>>(HWN, DD, CC,
        psT, CC, NC,  pwk, CC, 0,  pkt, DD, ND,  b_wk, 1, nullptr, 1.f, nullptr, 0, 0);
    // 3) scores1[n][m] = q·kt^T   (M=N=2304,K=64)
    hgemm2<false><<<dim3(18, 18, BB), blk>>>(HWN, HWN, DD,
        pq, DD, ND,  pkt, DD, ND,  pscores, HWN, NN,  nullptr, 0, nullptr, 1.f, nullptr, 0, 0);
    // 4) softmax -> S fp16 ; transpose -> ST
    softmax_h<<<BB * HWN, 256>>>(pscores, pS);
    th_kernel<<<dim3(HWN / 32, HWN / 32, BB), dim3(32, 8)>>>(pS, pST);
    // 5) v1[c][n] = wv1·qry + b  (M=512,N=2304,K=512), bias per-row c
    hgemm2<true><<<dim3(18, 4, BB), blk>>>(CC, HWN, CC,
        pwv1, CC, 0,  pqT, CC, NC,  pv1, HWN, (long)CC * HWN,  b_wv1, 2, nullptr, 1.f, nullptr, 0, 0);
    // 6) v2
    hgemm2<true><<<dim3(18, 4, BB), blk>>>(CC, HWN, CC,
        pwv2, CC, 0,  psT, CC, NC,  pv2, HWN, (long)CC * HWN,  b_wv2, 2, nullptr, 1.f, nullptr, 0, 0);
    // 7) x1[m][c] = gamma1·sum_n S[m][n]·v1[c][n] + qryT[m][c]  (M=2304,N=512,K=2304)
    hgemm2<true><<<dim3(4, 18, BB), blk>>>(HWN, CC, HWN,
        pS, HWN, NN,  pv1, HWN, (long)CC * HWN,  px1, CC, NC,
        nullptr, 0, gamma1, 1.f, pqT, CC, NC);
    // 8) x2[m][c] = gamma2·sum_n ST[m][n]·v2[c][n] + sptT[m][c]
    hgemm2<true><<<dim3(4, 18, BB), blk>>>(HWN, CC, HWN,
        pST, HWN, NN,  pv2, HWN, (long)CC * HWN,  px2, CC, NC,
        nullptr, 0, gamma2, 1.f, psT, CC, NC);
    // 9) q2[n][c2] = x1·ca_wq^T + b  (M=2304,N=512,K=512)
    hgemm2<true><<<dim3(4, 18, BB), blk>>>(HWN, CC, CC,
        px1, CC, NC,  pcq, CC, 0,  pq2, CC, NC,  ca_bq, 1, nullptr, 1.f, nullptr, 0, 0);
    // 10) k2
    hgemm2<true><<<dim3(4, 18, BB), blk>>>(HWN, CC, CC,
        px2, CC, NC,  pck, CC, 0,  pk2, CC, NC,  ca_bk, 1, nullptr, 1.f, nullptr, 0, 0);
    // 11) v2fT[c][m] = ca_wv·x2^T + b  (M=512,N=2304,K=512), bias per-row c
    hgemm2<true><<<dim3(18, 4, BB), blk>>>(CC, HWN, CC,
        pcv, CC, 0,  px2, CC, NC,  pv2fT, HWN, (long)CC * HWN,  ca_bv, 2, nullptr, 1.f, nullptr, 0, 0);
    // 12) scores2[n][m] = q2·k2^T /sqrt(C)  (M=N=2304,K=512)
    hgemm2<false><<<dim3(18, 18, BB), blk>>>(HWN, HWN, CC,
        pq2, CC, NC,  pk2, CC, NC,  pscores, HWN, NN,  nullptr, 0, nullptr, inv_sqrt_c, nullptr, 0, 0);
    // 13) softmax -> S2 fp16 (reuse h_S)
    softmax_h<<<BB * HWN, 256>>>(pscores, pS);
    // 14) mid[n][c] = sum_m S2[n][m]·v2fT[c][m]  (M=2304,N=512,K=2304)
    hgemm2<true><<<dim3(4, 18, BB), blk>>>(HWN, CC, HWN,
        pS, HWN, NN,  pv2fT, HWN, (long)CC * HWN,  pmid, CC, NC,
        nullptr, 0, nullptr, 1.f, nullptr, 0, 0);
    // 15) mid2[n][c] = mid·ca_wo^T + b -> fp32  (M=2304,N=512,K=512)
    hgemm2<false><<<dim3(4, 18, BB), blk>>>(HWN, CC, CC,
        pmid, CC, NC,  pco, CC, 0,  pmid2, CC, NC,  ca_bo, 1, nullptr, 1.f, nullptr, 0, 0);
    // 16) masked pooling -> proto
    proto_partial<<<dim3(18, BB), 512>>>(pmid2, mask, ppp, ppm);
    proto_reduce<<<BB, 512>>>(ppp, ppm, pproto);
    // 17) pf projections
    pf_gemv<<<dim3(CC / 8, 3, BB), 256>>>(pproto,
        pf_wq, pf_bq, pf_wk, pf_bk, pf_wv, pf_bv, pqp, pkp, pvp);
    // 18) aw[b] = qp[b]·kp[b]
    aw_kernel<<<BB, 256>>>(pqp, pkp, paw);
    // 19) softmax over batch + weighted sum -> out
    final_kernel<<<1, 512>>>(paw, pvp, (float*)d_out, out_size);
}